// round 11
// baseline (speedup 1.0000x reference)
#include <cuda_runtime.h>
#include <cuda_bf16.h>
#include <math.h>
#include <stdint.h>

#define T_   3072
#define DIM_ 1024
#define H_   8
#define D_   128

// ---------------- scratch (device globals: no allocation allowed) ----------
__device__ float g_gate[T_ * H_];
__device__ __nv_bfloat16 g_xh[(size_t)T_ * DIM_], g_xl[(size_t)T_ * DIM_];
__device__ __nv_bfloat16 g_wh[(size_t)4 * DIM_ * DIM_], g_wl[(size_t)4 * DIM_ * DIM_];
__device__ __nv_bfloat16 g_qh[(size_t)T_ * DIM_], g_ql[(size_t)T_ * DIM_];
__device__ __nv_bfloat16 g_kh[(size_t)T_ * DIM_], g_kl[(size_t)T_ * DIM_];
__device__ __nv_bfloat16 g_vh[(size_t)T_ * DIM_], g_vl[(size_t)T_ * DIM_];
__device__ __nv_bfloat16 g_yh[(size_t)T_ * DIM_], g_yl[(size_t)T_ * DIM_];

// ---------------- helpers ---------------------------------------------------
__device__ __forceinline__ void cpa16(unsigned dst, const void* src) {
    asm volatile("cp.async.cg.shared.global [%0],[%1],16;" :: "r"(dst), "l"(src));
}
#define CP_COMMIT() asm volatile("cp.async.commit_group;" ::: "memory")
#define CP_WAIT0()  asm volatile("cp.async.wait_group 0;" ::: "memory")

__device__ __forceinline__ void ldmx4(unsigned r[4], unsigned addr) {
    asm volatile("ldmatrix.sync.aligned.m8n8.x4.shared.b16 {%0,%1,%2,%3},[%4];"
                 : "=r"(r[0]), "=r"(r[1]), "=r"(r[2]), "=r"(r[3]) : "r"(addr));
}
__device__ __forceinline__ void ldmx4t(unsigned r[4], unsigned addr) {
    asm volatile("ldmatrix.sync.aligned.m8n8.x4.trans.shared.b16 {%0,%1,%2,%3},[%4];"
                 : "=r"(r[0]), "=r"(r[1]), "=r"(r[2]), "=r"(r[3]) : "r"(addr));
}
__device__ __forceinline__ void mma16816(float c[4], const unsigned a[4],
                                         const unsigned b0, const unsigned b1) {
    asm volatile("mma.sync.aligned.m16n8k16.row.col.f32.bf16.bf16.f32 "
                 "{%0,%1,%2,%3},{%4,%5,%6,%7},{%8,%9},{%0,%1,%2,%3};"
                 : "+f"(c[0]), "+f"(c[1]), "+f"(c[2]), "+f"(c[3])
                 : "r"(a[0]), "r"(a[1]), "r"(a[2]), "r"(a[3]), "r"(b0), "r"(b1));
}
__device__ __forceinline__ void split4(float4 v, uint2& h, uint2& l) {
    __nv_bfloat16 hx = __float2bfloat16(v.x), hy = __float2bfloat16(v.y);
    __nv_bfloat16 hz = __float2bfloat16(v.z), hw = __float2bfloat16(v.w);
    __nv_bfloat16 lx = __float2bfloat16(v.x - __bfloat162float(hx));
    __nv_bfloat16 ly = __float2bfloat16(v.y - __bfloat162float(hy));
    __nv_bfloat16 lz = __float2bfloat16(v.z - __bfloat162float(hz));
    __nv_bfloat16 lw = __float2bfloat16(v.w - __bfloat162float(hw));
    h.x = (unsigned)__bfloat16_as_ushort(hx) | ((unsigned)__bfloat16_as_ushort(hy) << 16);
    h.y = (unsigned)__bfloat16_as_ushort(hz) | ((unsigned)__bfloat16_as_ushort(hw) << 16);
    l.x = (unsigned)__bfloat16_as_ushort(lx) | ((unsigned)__bfloat16_as_ushort(ly) << 16);
    l.y = (unsigned)__bfloat16_as_ushort(lz) | ((unsigned)__bfloat16_as_ushort(lw) << 16);
}
__device__ __forceinline__ unsigned packsplit(float p0, float p1, unsigned& lo) {
    __nv_bfloat16 h0 = __float2bfloat16(p0), h1 = __float2bfloat16(p1);
    __nv_bfloat16 l0 = __float2bfloat16(p0 - __bfloat162float(h0));
    __nv_bfloat16 l1 = __float2bfloat16(p1 - __bfloat162float(h1));
    lo = (unsigned)__bfloat16_as_ushort(l0) | ((unsigned)__bfloat16_as_ushort(l1) << 16);
    return (unsigned)__bfloat16_as_ushort(h0) | ((unsigned)__bfloat16_as_ushort(h1) << 16);
}
__device__ __forceinline__ void store_split(__nv_bfloat16* ph, __nv_bfloat16* pl,
                                            size_t i, float v) {
    __nv_bfloat16 h = __float2bfloat16(v);
    ph[i] = h;
    pl[i] = __float2bfloat16(v - __bfloat162float(h));
}

// ---------------- one-time fp32 -> (hi,lo) bf16 conversion ------------------
__global__ __launch_bounds__(256) void convert_split(
    const float4* __restrict__ src, uint2* __restrict__ dh,
    uint2* __restrict__ dl, int n4)
{
    int i = blockIdx.x * 256 + threadIdx.x;
    if (i < n4) {
        uint2 h, l;
        split4(src[i], h, l);
        dh[i] = h; dl[i] = l;
    }
}

// ============================================================================
// GEMM smem layout (shared by both GEMM kernels)
// ============================================================================
#define ROWB  80
#define AHI_  0
#define ALO_  10240
#define BHI_  20480
#define BLO_  30720
#define BUFB  40960
#define GEMM_SMEM (2 * BUFB)

// main-loop body shared via macro (staging + mma), leaves acc[4][4][4] ready
#define GEMM_MAINLOOP(Ah, Al, Bh, Bl)                                          \
    float acc[4][4][4];                                                        \
    _Pragma("unroll")                                                          \
    for (int mi = 0; mi < 4; mi++)                                             \
        _Pragma("unroll")                                                      \
        for (int ni = 0; ni < 4; ni++)                                         \
            _Pragma("unroll")                                                  \
            for (int e = 0; e < 4; e++) acc[mi][ni][e] = 0.f;                  \
    auto stage = [&](int c, int buf) {                                         \
        const int kc = c * 32;                                                 \
        const unsigned bb = sb + buf * BUFB;                                   \
        _Pragma("unroll")                                                      \
        for (int i = 0; i < 2; i++) {                                          \
            int f = tid + i * 256;                                             \
            int row = f >> 2, q = f & 3;                                       \
            size_t ga = (size_t)(m0 + row) * 1024 + kc + q * 8;                \
            size_t gb = (size_t)(n0 + row) * 1024 + kc + q * 8;                \
            unsigned so = (unsigned)(row * ROWB + q * 16);                     \
            cpa16(bb + AHI_ + so, Ah + ga);                                    \
            cpa16(bb + ALO_ + so, Al + ga);                                    \
            cpa16(bb + BHI_ + so, Bh + gb);                                    \
            cpa16(bb + BLO_ + so, Bl + gb);                                    \
        }                                                                      \
        CP_COMMIT();                                                           \
    };                                                                         \
    const int a_row = lane & 15;                                               \
    const int a_kb  = (lane >> 4) * 16;                                        \
    const int b_nrl = ((lane >> 4) << 3) + (lane & 7);                         \
    const int b_kb  = ((lane >> 3) & 1) * 16;                                  \
    stage(0, 0);                                                               \
    for (int c = 0; c < 32; c++) {                                             \
        const int buf = c & 1;                                                 \
        CP_WAIT0();                                                            \
        __syncthreads();                                                       \
        if (c + 1 < 32) stage(c + 1, buf ^ 1);                                 \
        const unsigned base = sb + buf * BUFB;                                 \
        _Pragma("unroll")                                                      \
        for (int ks = 0; ks < 2; ks++) {                                       \
            unsigned ah[4][4], al[4][4], bh[4][2], bl[4][2];                   \
            _Pragma("unroll")                                                  \
            for (int mi = 0; mi < 4; mi++) {                                   \
                unsigned ad = base + AHI_ +                                    \
                    (unsigned)((wm0 + mi * 16 + a_row) * ROWB + ks * 32 + a_kb); \
                ldmx4(ah[mi], ad);                                             \
                ldmx4(al[mi], ad + (ALO_ - AHI_));                             \
            }                                                                  \
            _Pragma("unroll")                                                  \
            for (int p = 0; p < 2; p++) {                                      \
                unsigned bd = base + BHI_ +                                    \
                    (unsigned)((wn0 + p * 16 + b_nrl) * ROWB + ks * 32 + b_kb); \
                unsigned rr[4];                                                \
                ldmx4(rr, bd);                                                 \
                bh[2*p][0] = rr[0]; bh[2*p][1] = rr[1];                        \
                bh[2*p+1][0] = rr[2]; bh[2*p+1][1] = rr[3];                    \
                ldmx4(rr, bd + (BLO_ - BHI_));                                 \
                bl[2*p][0] = rr[0]; bl[2*p][1] = rr[1];                        \
                bl[2*p+1][0] = rr[2]; bl[2*p+1][1] = rr[3];                    \
            }                                                                  \
            _Pragma("unroll")                                                  \
            for (int mi = 0; mi < 4; mi++)                                     \
                _Pragma("unroll")                                              \
                for (int ni = 0; ni < 4; ni++) {                               \
                    mma16816(acc[mi][ni], ah[mi], bh[ni][0], bh[ni][1]);       \
                    mma16816(acc[mi][ni], al[mi], bh[ni][0], bh[ni][1]);       \
                    mma16816(acc[mi][ni], ah[mi], bl[ni][0], bl[ni][1]);       \
                }                                                              \
        }                                                                      \
    }

// ============================================================================
// GEMM2: plain fp32 epilogue (unchanged R9 behavior)
// ============================================================================
__global__ __launch_bounds__(256, 2) void gemm_bf16s(
    const __nv_bfloat16* __restrict__ Ah, const __nv_bfloat16* __restrict__ Al,
    const __nv_bfloat16* __restrict__ Bh, const __nv_bfloat16* __restrict__ Bl,
    float* __restrict__ C, int N, const float* __restrict__ lam, int lidx)
{
    extern __shared__ __align__(128) char smem[];
    const unsigned sb = (unsigned)__cvta_generic_to_shared(smem);
    const int tid  = threadIdx.x;
    const int wid  = tid >> 5;
    const int lane = tid & 31;
    const int m0 = blockIdx.y * 128;
    const int n0 = blockIdx.x * 128;
    const int wm0 = (wid & 1) * 64;
    const int wn0 = (wid >> 1) * 32;

    GEMM_MAINLOOP(Ah, Al, Bh, Bl)

    const float alpha = lam[lidx];
    const int r  = lane >> 2;
    const int cc = (lane & 3) * 2;
#pragma unroll
    for (int mi = 0; mi < 4; mi++)
#pragma unroll
        for (int ni = 0; ni < 4; ni++) {
            const int row = m0 + wm0 + mi * 16 + r;
            const int col = n0 + wn0 + ni * 8 + cc;
            float2 w0; w0.x = alpha * acc[mi][ni][0]; w0.y = alpha * acc[mi][ni][1];
            float2 w1; w1.x = alpha * acc[mi][ni][2]; w1.y = alpha * acc[mi][ni][3];
            *(float2*)(C + (size_t)row * N + col) = w0;
            *(float2*)(C + (size_t)(row + 8) * N + col) = w1;
        }
}

// ============================================================================
// GEMM1 with fused postproc epilogue. n-tile = one head of q, k, or v.
//   type = blockIdx.x>>3 (0=q,1=k,2=v), head = blockIdx.x&7
//   q/k: rmsnorm + rotary -> split planes.  v: +veg*ve -> planes; gates.
// ============================================================================
#define VB_OFF  0        // fp32 vbuf[128][132] = 67584 B
#define SQ_OFF  67584    // fp32 ssqb[4][128]   = 2048 B
#define GB_OFF  69632    // fp32 gbuf[128]      = 512 B

__global__ __launch_bounds__(256, 2) void gemm1_fused(
    const __nv_bfloat16* __restrict__ Ah, const __nv_bfloat16* __restrict__ Al,
    const __nv_bfloat16* __restrict__ Bh, const __nv_bfloat16* __restrict__ Bl,
    const float* __restrict__ x, const float* __restrict__ ve,
    const float* __restrict__ vgw, const float* __restrict__ agw,
    const float* __restrict__ cosb, const float* __restrict__ sinb,
    const float* __restrict__ lam)
{
    extern __shared__ __align__(128) char smem[];
    const unsigned sb = (unsigned)__cvta_generic_to_shared(smem);
    const int tid  = threadIdx.x;
    const int wid  = tid >> 5;
    const int lane = tid & 31;
    const int m0 = blockIdx.y * 128;
    const int n0 = blockIdx.x * 128;
    const int wm0 = (wid & 1) * 64;
    const int wn0 = (wid >> 1) * 32;

    GEMM_MAINLOOP(Ah, Al, Bh, Bl)

    __syncthreads();   // staging buffers now free for epilogue reuse

    const float alpha = lam[0];
    const int head = blockIdx.x & 7;
    const int type = blockIdx.x >> 3;
    const int r   = lane >> 2;
    const int c_  = lane & 3;
    const int cc  = c_ * 2;
    float* vbuf = (float*)(smem + VB_OFF);
    float* ssqb = (float*)(smem + SQ_OFF);
    float* gbuf = (float*)(smem + GB_OFF);

    if (type < 2) {
        // ---- rmsnorm: scale by lam, ssq partials, 4-lane shuffle, smem ----
#pragma unroll
        for (int mi = 0; mi < 4; mi++) {
            float p1 = 0.f, p2 = 0.f;
#pragma unroll
            for (int ni = 0; ni < 4; ni++) {
                acc[mi][ni][0] *= alpha; acc[mi][ni][1] *= alpha;
                acc[mi][ni][2] *= alpha; acc[mi][ni][3] *= alpha;
                p1 += acc[mi][ni][0]*acc[mi][ni][0] + acc[mi][ni][1]*acc[mi][ni][1];
                p2 += acc[mi][ni][2]*acc[mi][ni][2] + acc[mi][ni][3]*acc[mi][ni][3];
            }
            p1 += __shfl_xor_sync(0xffffffffu, p1, 1);
            p1 += __shfl_xor_sync(0xffffffffu, p1, 2);
            p2 += __shfl_xor_sync(0xffffffffu, p2, 1);
            p2 += __shfl_xor_sync(0xffffffffu, p2, 2);
            if (c_ == 0) {
                int slice = wid >> 1;
                ssqb[slice * 128 + wm0 + mi * 16 + r]     = p1;
                ssqb[slice * 128 + wm0 + mi * 16 + r + 8] = p2;
            }
        }
        __syncthreads();
        // ---- normalize into vbuf ----
#pragma unroll
        for (int mi = 0; mi < 4; mi++) {
            int row1 = wm0 + mi * 16 + r, row2 = row1 + 8;
            float s1 = ssqb[row1] + ssqb[128+row1] + ssqb[256+row1] + ssqb[384+row1];
            float s2 = ssqb[row2] + ssqb[128+row2] + ssqb[256+row2] + ssqb[384+row2];
            float rr1 = rsqrtf(s1 * (1.0f/128.0f) + 1e-6f);
            float rr2 = rsqrtf(s2 * (1.0f/128.0f) + 1e-6f);
#pragma unroll
            for (int ni = 0; ni < 4; ni++) {
                int col = wn0 + ni * 8 + cc;
                vbuf[row1 * 132 + col]     = acc[mi][ni][0] * rr1;
                vbuf[row1 * 132 + col + 1] = acc[mi][ni][1] * rr1;
                vbuf[row2 * 132 + col]     = acc[mi][ni][2] * rr2;
                vbuf[row2 * 132 + col + 1] = acc[mi][ni][3] * rr2;
            }
        }
        __syncthreads();
        // ---- rotary + split-store ----
        __nv_bfloat16* ph = (type == 0) ? g_qh : g_kh;
        __nv_bfloat16* pl = (type == 0) ? g_ql : g_kl;
        const int dl = tid & 63, rb = tid >> 6;
#pragma unroll 4
        for (int it = 0; it < 32; it++) {
            int row = rb + it * 4;
            int t = m0 + row;
            float a = vbuf[row * 132 + dl];
            float b = vbuf[row * 132 + 64 + dl];
            float cs = cosb[t * 64 + dl], sn = sinb[t * 64 + dl];
            size_t ob = (size_t)t * DIM_ + head * D_ + dl;
            store_split(ph, pl, ob,       a * cs + b * sn);
            store_split(ph, pl, ob + 64, -a * sn + b * cs);
        }
    } else {
        // ---- v: gates, then v = lam*acc + veg*ve ----
        if (tid < 128) {
            int t = m0 + tid;
            float dv = 0.f, da = 0.f;
#pragma unroll
            for (int i = 0; i < 16; i++) {
                float xv = x[(size_t)t * DIM_ + i];
                dv += xv * vgw[head * 16 + i];
                da += xv * agw[head * 16 + i];
            }
            gbuf[tid] = 2.0f / (1.0f + __expf(-dv));
            g_gate[t * H_ + head] = 1.0f / (1.0f + __expf(-da));
        }
        __syncthreads();
#pragma unroll
        for (int mi = 0; mi < 4; mi++) {
            int row1 = wm0 + mi * 16 + r, row2 = row1 + 8;
            float vg1 = gbuf[row1], vg2 = gbuf[row2];
#pragma unroll
            for (int ni = 0; ni < 4; ni++) {
                int col = wn0 + ni * 8 + cc;
                size_t i1 = (size_t)(m0 + row1) * DIM_ + head * D_ + col;
                size_t i2 = (size_t)(m0 + row2) * DIM_ + head * D_ + col;
                float2 e1 = *(const float2*)(ve + i1);
                float2 e2 = *(const float2*)(ve + i2);
                unsigned lw, hw;
                hw = packsplit(acc[mi][ni][0]*alpha + vg1*e1.x,
                               acc[mi][ni][1]*alpha + vg1*e1.y, lw);
                *(unsigned*)(g_vh + i1) = hw;
                *(unsigned*)(g_vl + i1) = lw;
                hw = packsplit(acc[mi][ni][2]*alpha + vg2*e2.x,
                               acc[mi][ni][3]*alpha + vg2*e2.y, lw);
                *(unsigned*)(g_vh + i2) = hw;
                *(unsigned*)(g_vl + i2) = lw;
            }
        }
    }
}

// ============================================================================
// flash attention (exact R9 version: 4 warps, cp.async staging, heavy-first)
// ============================================================================
#define KSTR2 136
#define QH_ 0
#define QL_ 8704
#define KH_ 17408
#define KL_ 26112
#define VH_ 34816
#define VL_ 43520
#define ATTN2_SMEM (104448 + 256)

__global__ __launch_bounds__(128) void attn_mma(
    const int* __restrict__ seg, const int* __restrict__ bm_ptr)
{
    extern __shared__ __align__(128) __nv_bfloat16 sm2[];
    int* kseg = (int*)((char*)sm2 + 104448);
    const unsigned sb = (unsigned)__cvta_generic_to_shared(sm2);
    const int h   = blockIdx.y;
    const int m0  = ((int)gridDim.x - 1 - (int)blockIdx.x) * 64;  // heavy first
    const int tid = threadIdx.x;
    const int wid = tid >> 5, lane = tid & 31;
    const int bm  = bm_ptr[0];
    const int wr  = wid * 16;

#pragma unroll
    for (int i = 0; i < 8; i++) {
        int f = tid + i * 128;
        int r = f >> 4, u = f & 15;
        size_t ga = (size_t)(m0 + r) * DIM_ + h * D_ + u * 8;
        cpa16(sb + (unsigned)(QH_ + r * KSTR2 + u * 8) * 2, g_qh + ga);
        cpa16(sb + (unsigned)(QL_ + r * KSTR2 + u * 8) * 2, g_ql + ga);
    }
    CP_COMMIT();

    const int r_ = lane >> 2, c_ = lane & 3;
    const int tq0 = m0 + wr + r_, tq1 = tq0 + 8;
    const int sq0 = seg[tq0], sq1 = seg[tq1];

    float mi0 = -1e30f, mi1 = -1e30f, li0 = 0.f, li1 = 0.f;
    float o[16][4];
#pragma unroll
    for (int t = 0; t < 16; t++)
#pragma unroll
        for (int e = 0; e < 4; e++) o[t][e] = 0.f;

    const unsigned a_addr = sb + (unsigned)(QH_ + (wr + (lane & 15)) * KSTR2 + (lane >> 4) * 8) * 2;
    const int g  = lane >> 3, gl = lane & 7;
    const unsigned kb_addr = sb + (unsigned)(KH_ + ((g >> 1) * 8 + gl) * KSTR2 + (g & 1) * 8) * 2;
    const unsigned vb_addr = sb + (unsigned)(VH_ + ((g & 1) * 8 + gl) * KSTR2 + (g >> 1) * 8) * 2;

    const int qs0 = seg[m0], qs1 = seg[m0 + 63];
    int kb_lo = m0 - bm; if (kb_lo < 0) kb_lo = 0; kb_lo >>= 6;
    const int kb_hi = m0 >> 6;

    for (int kb = kb_lo; kb <= kb_hi; kb++) {
        const int s0 = kb * 64;
        if (seg[s0 + 63] < qs0 || seg[s0] > qs1) continue;

        __syncthreads();
#pragma unroll
        for (int i = 0; i < 8; i++) {
            int f = tid + i * 128;
            int r = f >> 4, u = f & 15;
            int t = s0 + r;
            int ts = ((u >> 2) & 1) ? (t > 0 ? t - 1 : 0) : t;
            size_t gk = (size_t)ts * DIM_ + h * D_ + u * 8;
            size_t gv = (size_t)t  * DIM_ + h * D_ + u * 8;
            cpa16(sb + (unsigned)(KH_ + r * KSTR2 + u * 8) * 2, g_kh + gk);
            cpa16(sb + (unsigned)(KL_ + r * KSTR2 + u * 8) * 2, g_kl + gk);
            cpa16(sb + (unsigned)(VH_ + r * KSTR2 + u * 8) * 2, g_vh + gv);
            cpa16(sb + (unsigned)(VL_ + r * KSTR2 + u * 8) * 2, g_vl + gv);
        }
        CP_COMMIT();
        if (tid < 64) kseg[tid] = seg[s0 + tid];
        CP_WAIT0();
        __syncthreads();

        float s[8][4];
#pragma unroll
        for (int j = 0; j < 8; j++)
#pragma unroll
            for (int e = 0; e < 4; e++) s[j][e] = 0.f;

#pragma unroll
        for (int kk = 0; kk < 8; kk++) {
            unsigned ah[4], al[4];
            ldmx4(ah, a_addr + kk * 32);
            ldmx4(al, a_addr + (QL_ - QH_) * 2 + kk * 32);
#pragma unroll
            for (int jp = 0; jp < 4; jp++) {
                unsigned bh[4], bl[4];
                unsigned ba = kb_addr + (unsigned)(jp * 16 * KSTR2) * 2 + kk * 32;
                ldmx4(bh, ba);
                ldmx4(bl, ba + (KL_ - KH_) * 2);
                mma16816(s[2*jp],   ah, bh[0], bh[1]);
                mma16816(s[2*jp],   al, bh[0], bh[1]);
                mma16816(s[2*jp],   ah, bl[0], bl[1]);
                mma16816(s[2*jp+1], ah, bh[2], bh[3]);
                mma16816(s[2*jp+1], al, bh[2], bh[3]);
                mma16816(s[2*jp+1], ah, bl[2], bl[3]);
            }
        }

        float mx0 = -1e30f, mx1 = -1e30f;
#pragma unroll
        for (int j = 0; j < 8; j++) {
            const int nb = 8 * j + 2 * c_;
            const int tk0 = s0 + nb, tk1 = tk0 + 1;
            const int ka = kseg[nb], kb2 = kseg[nb + 1];
            bool v00 = (tk0 <= tq0) && (tk0 >= tq0 - bm) && (ka  == sq0);
            bool v01 = (tk1 <= tq0) && (tk1 >= tq0 - bm) && (kb2 == sq0);
            bool v10 = (tk0 <= tq1) && (tk0 >= tq1 - bm) && (ka  == sq1);
            bool v11 = (tk1 <= tq1) && (tk1 >= tq1 - bm) && (kb2 == sq1);
            s[j][0] = v00 ? s[j][0] * 0.1f : -1e30f;
            s[j][1] = v01 ? s[j][1] * 0.1f : -1e30f;
            s[j][2] = v10 ? s[j][2] * 0.1f : -1e30f;
            s[j][3] = v11 ? s[j][3] * 0.1f : -1e30f;
            mx0 = fmaxf(mx0, fmaxf(s[j][0], s[j][1]));
            mx1 = fmaxf(mx1, fmaxf(s[j][2], s[j][3]));
        }
        mx0 = fmaxf(mx0, __shfl_xor_sync(0xffffffffu, mx0, 1));
        mx0 = fmaxf(mx0, __shfl_xor_sync(0xffffffffu, mx0, 2));
        mx1 = fmaxf(mx1, __shfl_xor_sync(0xffffffffu, mx1, 1));
        mx1 = fmaxf(mx1, __shfl_xor_sync(0xffffffffu, mx1, 2));

        const float nm0 = fmaxf(mi0, mx0), nm1 = fmaxf(mi1, mx1);
        const float al0 = __expf(mi0 - nm0), al1 = __expf(mi1 - nm1);
        mi0 = nm0; mi1 = nm1;
        float rs0 = 0.f, rs1 = 0.f;
#pragma unroll
        for (int j = 0; j < 8; j++) {
            s[j][0] = __expf(s[j][0] - nm0);
            s[j][1] = __expf(s[j][1] - nm0);
            s[j][2] = __expf(s[j][2] - nm1);
            s[j][3] = __expf(s[j][3] - nm1);
            rs0 += s[j][0] + s[j][1];
            rs1 += s[j][2] + s[j][3];
        }
        rs0 += __shfl_xor_sync(0xffffffffu, rs0, 1);
        rs0 += __shfl_xor_sync(0xffffffffu, rs0, 2);
        rs1 += __shfl_xor_sync(0xffffffffu, rs1, 1);
        rs1 += __shfl_xor_sync(0xffffffffu, rs1, 2);
        li0 = li0 * al0 + rs0;
        li1 = li1 * al1 + rs1;
#pragma unroll
        for (int t = 0; t < 16; t++) {
            o[t][0] *= al0; o[t][1] *= al0;
            o[t][2] *= al1; o[t][3] *= al1;
        }

#pragma unroll
        for (int ss = 0; ss < 4; ss++) {
            unsigned pha[4], pla[4];
            pha[0] = packsplit(s[2*ss][0],   s[2*ss][1],   pla[0]);
            pha[1] = packsplit(s[2*ss][2],   s[2*ss][3],   pla[1]);
            pha[2] = packsplit(s[2*ss+1][0], s[2*ss+1][1], pla[2]);
            pha[3] = packsplit(s[2*ss+1][2], s[2*ss+1][3], pla[3]);
#pragma unroll
            for (int dp = 0; dp < 8; dp++) {
                unsigned bh[4], bl[4];
                unsigned ba = vb_addr + (unsigned)(ss * 16 * KSTR2) * 2 + dp * 32;
                ldmx4t(bh, ba);
                ldmx4t(bl, ba + (VL_ - VH_) * 2);
                mma16816(o[2*dp],   pha, bh[0], bh[1]);
                mma16816(o[2*dp],   pla, bh[0], bh[1]);
                mma16816(o[2*dp],   pha, bl[0], bl[1]);
                mma16816(o[2*dp+1], pha, bh[2], bh[3]);
                mma16816(o[2*dp+1], pla, bh[2], bh[3]);
                mma16816(o[2*dp+1], pha, bl[2], bl[3]);
            }
        }
    }

    const float gg0 = g_gate[tq0 * H_ + h], gg1 = g_gate[tq1 * H_ + h];
    const float i0 = gg0 / li0, i1 = gg1 / li1;
#pragma unroll
    for (int t = 0; t < 16; t++) {
        size_t idx0 = (size_t)tq0 * DIM_ + h * D_ + 8 * t + 2 * c_;
        size_t idx1 = (size_t)tq1 * DIM_ + h * D_ + 8 * t + 2 * c_;
        unsigned lw;
        unsigned hw = packsplit(o[t][0] * i0, o[t][1] * i0, lw);
        *(unsigned*)(g_yh + idx0) = hw;
        *(unsigned*)(g_yl + idx0) = lw;
        hw = packsplit(o[t][2] * i1, o[t][3] * i1, lw);
        *(unsigned*)(g_yh + idx1) = hw;
        *(unsigned*)(g_yl + idx1) = lw;
    }
}

// ---------------------------------------------------------------------------
extern "C" void kernel_launch(void* const* d_in, const int* in_sizes, int n_in,
                              void* d_out, int out_size)
{
    const float* x    = (const float*)d_in[0];
    const float* qkvo = (const float*)d_in[1];
    const float* lam  = (const float*)d_in[2];
    const float* ve   = (const float*)d_in[3];
    const float* agw  = (const float*)d_in[4];
    const float* vgw  = (const float*)d_in[5];
    const float* cosb = (const float*)d_in[6];
    const float* sinb = (const float*)d_in[7];
    const int*   seg  = (const int*)d_in[8];
    const int*   bmp  = (const int*)d_in[9];
    float*       out  = (float*)d_out;

    __nv_bfloat16 *p_xh, *p_xl, *p_wh, *p_wl, *p_yh, *p_yl;
    cudaGetSymbolAddress((void**)&p_xh, g_xh);
    cudaGetSymbolAddress((void**)&p_xl, g_xl);
    cudaGetSymbolAddress((void**)&p_wh, g_wh);
    cudaGetSymbolAddress((void**)&p_wl, g_wl);
    cudaGetSymbolAddress((void**)&p_yh, g_yh);
    cudaGetSymbolAddress((void**)&p_yl, g_yl);

    cudaFuncSetAttribute(gemm_bf16s,
                         cudaFuncAttributeMaxDynamicSharedMemorySize, GEMM_SMEM);
    cudaFuncSetAttribute(gemm1_fused,
                         cudaFuncAttributeMaxDynamicSharedMemorySize, GEMM_SMEM);
    cudaFuncSetAttribute(attn_mma,
                         cudaFuncAttributeMaxDynamicSharedMemorySize, ATTN2_SMEM);

    // 0. one-time splits
    convert_split<<<T_ * DIM_ / 1024, 256>>>((const float4*)x,
                                             (uint2*)p_xh, (uint2*)p_xl,
                                             T_ * DIM_ / 4);
    convert_split<<<4 * DIM_ * DIM_ / 1024, 256>>>((const float4*)qkvo,
                                                   (uint2*)p_wh, (uint2*)p_wl,
                                                   4 * DIM_ * DIM_ / 4);

    // 1. qkv projection + fused rmsnorm/rotary/gates/ve -> split planes
    gemm1_fused<<<dim3(24, 24), 256, GEMM_SMEM>>>(
        p_xh, p_xl, p_wh, p_wl, x, ve, vgw, agw, cosb, sinb, lam);

    // 2. attention (tensor cores; k-shift fused; heavy-first)
    attn_mma<<<dim3(T_ / 64, H_), 128, ATTN2_SMEM>>>(seg, bmp);

    // 3. out = lam1 * y @ Wo^T   [3072 x 1024]
    gemm_bf16s<<<dim3(8, 24), 256, GEMM_SMEM>>>(
        p_yh, p_yl, p_wh + (size_t)3 * DIM_ * DIM_, p_wl + (size_t)3 * DIM_ * DIM_,
        out, 1024, lam, 1);
}

// round 12
// speedup vs baseline: 1.4221x; 1.4221x over previous
#include <cuda_runtime.h>
#include <cuda_bf16.h>
#include <math.h>
#include <stdint.h>

#define T_   3072
#define DIM_ 1024
#define H_   8
#define D_   128

// ---------------- scratch (device globals: no allocation allowed) ----------
__device__ float g_qkv[(size_t)T_ * 3 * DIM_];
__device__ float g_gate[T_ * H_];
__device__ __nv_bfloat16 g_xh[(size_t)T_ * DIM_], g_xl[(size_t)T_ * DIM_];
__device__ __nv_bfloat16 g_wh[(size_t)4 * DIM_ * DIM_], g_wl[(size_t)4 * DIM_ * DIM_];
__device__ __nv_bfloat16 g_qh[(size_t)T_ * DIM_], g_ql[(size_t)T_ * DIM_];
__device__ __nv_bfloat16 g_kh[(size_t)T_ * DIM_], g_kl[(size_t)T_ * DIM_];
__device__ __nv_bfloat16 g_vh[(size_t)T_ * DIM_], g_vl[(size_t)T_ * DIM_];
__device__ __nv_bfloat16 g_yh[(size_t)T_ * DIM_], g_yl[(size_t)T_ * DIM_];

// ---------------- helpers ---------------------------------------------------
__device__ __forceinline__ void cpa16(unsigned dst, const void* src) {
    asm volatile("cp.async.cg.shared.global [%0],[%1],16;" :: "r"(dst), "l"(src));
}
#define CP_COMMIT() asm volatile("cp.async.commit_group;" ::: "memory")
#define CP_WAIT0()  asm volatile("cp.async.wait_group 0;" ::: "memory")

__device__ __forceinline__ void ldmx4(unsigned r[4], unsigned addr) {
    asm volatile("ldmatrix.sync.aligned.m8n8.x4.shared.b16 {%0,%1,%2,%3},[%4];"
                 : "=r"(r[0]), "=r"(r[1]), "=r"(r[2]), "=r"(r[3]) : "r"(addr));
}
__device__ __forceinline__ void ldmx4t(unsigned r[4], unsigned addr) {
    asm volatile("ldmatrix.sync.aligned.m8n8.x4.trans.shared.b16 {%0,%1,%2,%3},[%4];"
                 : "=r"(r[0]), "=r"(r[1]), "=r"(r[2]), "=r"(r[3]) : "r"(addr));
}
__device__ __forceinline__ void mma16816(float c[4], const unsigned a[4],
                                         const unsigned b0, const unsigned b1) {
    asm volatile("mma.sync.aligned.m16n8k16.row.col.f32.bf16.bf16.f32 "
                 "{%0,%1,%2,%3},{%4,%5,%6,%7},{%8,%9},{%0,%1,%2,%3};"
                 : "+f"(c[0]), "+f"(c[1]), "+f"(c[2]), "+f"(c[3])
                 : "r"(a[0]), "r"(a[1]), "r"(a[2]), "r"(a[3]), "r"(b0), "r"(b1));
}
__device__ __forceinline__ void split4(float4 v, uint2& h, uint2& l) {
    __nv_bfloat16 hx = __float2bfloat16(v.x), hy = __float2bfloat16(v.y);
    __nv_bfloat16 hz = __float2bfloat16(v.z), hw = __float2bfloat16(v.w);
    __nv_bfloat16 lx = __float2bfloat16(v.x - __bfloat162float(hx));
    __nv_bfloat16 ly = __float2bfloat16(v.y - __bfloat162float(hy));
    __nv_bfloat16 lz = __float2bfloat16(v.z - __bfloat162float(hz));
    __nv_bfloat16 lw = __float2bfloat16(v.w - __bfloat162float(hw));
    h.x = (unsigned)__bfloat16_as_ushort(hx) | ((unsigned)__bfloat16_as_ushort(hy) << 16);
    h.y = (unsigned)__bfloat16_as_ushort(hz) | ((unsigned)__bfloat16_as_ushort(hw) << 16);
    l.x = (unsigned)__bfloat16_as_ushort(lx) | ((unsigned)__bfloat16_as_ushort(ly) << 16);
    l.y = (unsigned)__bfloat16_as_ushort(lz) | ((unsigned)__bfloat16_as_ushort(lw) << 16);
}
__device__ __forceinline__ unsigned packsplit(float p0, float p1, unsigned& lo) {
    __nv_bfloat16 h0 = __float2bfloat16(p0), h1 = __float2bfloat16(p1);
    __nv_bfloat16 l0 = __float2bfloat16(p0 - __bfloat162float(h0));
    __nv_bfloat16 l1 = __float2bfloat16(p1 - __bfloat162float(h1));
    lo = (unsigned)__bfloat16_as_ushort(l0) | ((unsigned)__bfloat16_as_ushort(l1) << 16);
    return (unsigned)__bfloat16_as_ushort(h0) | ((unsigned)__bfloat16_as_ushort(h1) << 16);
}
__device__ __forceinline__ void store_split(__nv_bfloat16* ph, __nv_bfloat16* pl,
                                            size_t i, float v) {
    __nv_bfloat16 h = __float2bfloat16(v);
    ph[i] = h;
    pl[i] = __float2bfloat16(v - __bfloat162float(h));
}

// ---------------- one-time fp32 -> (hi,lo) bf16 conversion ------------------
__global__ __launch_bounds__(256) void convert_split(
    const float4* __restrict__ src, uint2* __restrict__ dh,
    uint2* __restrict__ dl, int n4)
{
    int i = blockIdx.x * 256 + threadIdx.x;
    if (i < n4) {
        uint2 h, l;
        split4(src[i], h, l);
        dh[i] = h; dl[i] = l;
    }
}

// ============================================================================
// bf16-split mma.sync GEMM, cp.async staging; 2 CTAs/SM (R9 WIN, unchanged)
// ============================================================================
#define ROWB  80
#define AHI_  0
#define ALO_  10240
#define BHI_  20480
#define BLO_  30720
#define BUFB  40960
#define GEMM_SMEM (2 * BUFB)

__global__ __launch_bounds__(256, 2) void gemm_bf16s(
    const __nv_bfloat16* __restrict__ Ah, const __nv_bfloat16* __restrict__ Al,
    const __nv_bfloat16* __restrict__ Bh, const __nv_bfloat16* __restrict__ Bl,
    float* __restrict__ C, int N, const float* __restrict__ lam, int lidx)
{
    extern __shared__ __align__(128) char smem[];
    const unsigned sb = (unsigned)__cvta_generic_to_shared(smem);
    const int tid  = threadIdx.x;
    const int wid  = tid >> 5;
    const int lane = tid & 31;
    const int m0 = blockIdx.y * 128;
    const int n0 = blockIdx.x * 128;
    const int wm0 = (wid & 1) * 64;
    const int wn0 = (wid >> 1) * 32;

    float acc[4][4][4];
#pragma unroll
    for (int mi = 0; mi < 4; mi++)
#pragma unroll
        for (int ni = 0; ni < 4; ni++)
#pragma unroll
            for (int e = 0; e < 4; e++) acc[mi][ni][e] = 0.f;

    auto stage = [&](int c, int buf) {
        const int kc = c * 32;
        const unsigned bb = sb + buf * BUFB;
#pragma unroll
        for (int i = 0; i < 2; i++) {
            int f = tid + i * 256;
            int row = f >> 2, q = f & 3;
            size_t ga = (size_t)(m0 + row) * 1024 + kc + q * 8;
            size_t gb = (size_t)(n0 + row) * 1024 + kc + q * 8;
            unsigned so = (unsigned)(row * ROWB + q * 16);
            cpa16(bb + AHI_ + so, Ah + ga);
            cpa16(bb + ALO_ + so, Al + ga);
            cpa16(bb + BHI_ + so, Bh + gb);
            cpa16(bb + BLO_ + so, Bl + gb);
        }
        CP_COMMIT();
    };

    const int a_row = lane & 15;
    const int a_kb  = (lane >> 4) * 16;
    const int b_nrl = ((lane >> 4) << 3) + (lane & 7);
    const int b_kb  = ((lane >> 3) & 1) * 16;

    stage(0, 0);

    for (int c = 0; c < 32; c++) {
        const int buf = c & 1;
        CP_WAIT0();
        __syncthreads();
        if (c + 1 < 32) stage(c + 1, buf ^ 1);

        const unsigned base = sb + buf * BUFB;
#pragma unroll
        for (int ks = 0; ks < 2; ks++) {
            unsigned ah[4][4], al[4][4], bh[4][2], bl[4][2];
#pragma unroll
            for (int mi = 0; mi < 4; mi++) {
                unsigned ad = base + AHI_ +
                    (unsigned)((wm0 + mi * 16 + a_row) * ROWB + ks * 32 + a_kb);
                ldmx4(ah[mi], ad);
                ldmx4(al[mi], ad + (ALO_ - AHI_));
            }
#pragma unroll
            for (int p = 0; p < 2; p++) {
                unsigned bd = base + BHI_ +
                    (unsigned)((wn0 + p * 16 + b_nrl) * ROWB + ks * 32 + b_kb);
                unsigned r[4];
                ldmx4(r, bd);
                bh[2*p][0] = r[0]; bh[2*p][1] = r[1];
                bh[2*p+1][0] = r[2]; bh[2*p+1][1] = r[3];
                ldmx4(r, bd + (BLO_ - BHI_));
                bl[2*p][0] = r[0]; bl[2*p][1] = r[1];
                bl[2*p+1][0] = r[2]; bl[2*p+1][1] = r[3];
            }
#pragma unroll
            for (int mi = 0; mi < 4; mi++)
#pragma unroll
                for (int ni = 0; ni < 4; ni++) {
                    mma16816(acc[mi][ni], ah[mi], bh[ni][0], bh[ni][1]);
                    mma16816(acc[mi][ni], al[mi], bh[ni][0], bh[ni][1]);
                    mma16816(acc[mi][ni], ah[mi], bl[ni][0], bl[ni][1]);
                }
        }
    }

    const float alpha = lam[lidx];
    const int r  = lane >> 2;
    const int cc = (lane & 3) * 2;
#pragma unroll
    for (int mi = 0; mi < 4; mi++)
#pragma unroll
        for (int ni = 0; ni < 4; ni++) {
            const int row = m0 + wm0 + mi * 16 + r;
            const int col = n0 + wn0 + ni * 8 + cc;
            float2 w0; w0.x = alpha * acc[mi][ni][0]; w0.y = alpha * acc[mi][ni][1];
            float2 w1; w1.x = alpha * acc[mi][ni][2]; w1.y = alpha * acc[mi][ni][3];
            *(float2*)(C + (size_t)row * N + col) = w0;
            *(float2*)(C + (size_t)(row + 8) * N + col) = w1;
        }
}

// ------------- postprocess: rmsnorm + rotary + gates + ve; split-bf16 out --
__global__ __launch_bounds__(256) void postproc_kernel(
    const float* __restrict__ x, const float* __restrict__ ve,
    const float* __restrict__ ve_gate_w, const float* __restrict__ attn_gate_w,
    const float* __restrict__ cosb, const float* __restrict__ sinb)
{
    const int t    = blockIdx.x;
    const int w    = threadIdx.x >> 5;
    const int lane = threadIdx.x & 31;
    const float* base = g_qkv + (size_t)t * (3 * DIM_);
    const size_t ob = (size_t)t * DIM_ + w * D_;

    const float c0 = cosb[t * 64 + lane],      s0 = sinb[t * 64 + lane];
    const float c1 = cosb[t * 64 + lane + 32], s1 = sinb[t * 64 + lane + 32];

    {
        const float* qb = base + w * D_;
        float a0 = qb[lane], a1 = qb[lane + 32], a2 = qb[lane + 64], a3 = qb[lane + 96];
        float ss = a0*a0 + a1*a1 + a2*a2 + a3*a3;
#pragma unroll
        for (int off = 16; off; off >>= 1) ss += __shfl_xor_sync(0xffffffffu, ss, off);
        float r = rsqrtf(ss * (1.0f / 128.0f) + 1e-6f);
        a0 *= r; a1 *= r; a2 *= r; a3 *= r;
        store_split(g_qh, g_ql, ob + lane,       a0 * c0 + a2 * s0);
        store_split(g_qh, g_ql, ob + lane + 32,  a1 * c1 + a3 * s1);
        store_split(g_qh, g_ql, ob + lane + 64, -a0 * s0 + a2 * c0);
        store_split(g_qh, g_ql, ob + lane + 96, -a1 * s1 + a3 * c1);
    }
    {
        const float* kb = base + DIM_ + w * D_;
        float a0 = kb[lane], a1 = kb[lane + 32], a2 = kb[lane + 64], a3 = kb[lane + 96];
        float ss = a0*a0 + a1*a1 + a2*a2 + a3*a3;
#pragma unroll
        for (int off = 16; off; off >>= 1) ss += __shfl_xor_sync(0xffffffffu, ss, off);
        float r = rsqrtf(ss * (1.0f / 128.0f) + 1e-6f);
        a0 *= r; a1 *= r; a2 *= r; a3 *= r;
        store_split(g_kh, g_kl, ob + lane,       a0 * c0 + a2 * s0);
        store_split(g_kh, g_kl, ob + lane + 32,  a1 * c1 + a3 * s1);
        store_split(g_kh, g_kl, ob + lane + 64, -a0 * s0 + a2 * c0);
        store_split(g_kh, g_kl, ob + lane + 96, -a1 * s1 + a3 * c1);
    }
    float xv = (lane < 16) ? x[(size_t)t * DIM_ + lane] : 0.f;
    float dv = (lane < 16) ? xv * ve_gate_w[w * 16 + lane]   : 0.f;
    float da = (lane < 16) ? xv * attn_gate_w[w * 16 + lane] : 0.f;
#pragma unroll
    for (int off = 16; off; off >>= 1) {
        dv += __shfl_xor_sync(0xffffffffu, dv, off);
        da += __shfl_xor_sync(0xffffffffu, da, off);
    }
    const float veg = 2.0f / (1.0f + __expf(-dv));
    if (lane == 0) g_gate[t * H_ + w] = 1.0f / (1.0f + __expf(-da));
    {
        const float* vb  = base + 2 * DIM_ + w * D_;
        const float* vp2 = ve + ob;
        store_split(g_vh, g_vl, ob + lane,      vb[lane]      + veg * vp2[lane]);
        store_split(g_vh, g_vl, ob + lane + 32, vb[lane + 32] + veg * vp2[lane + 32]);
        store_split(g_vh, g_vl, ob + lane + 64, vb[lane + 64] + veg * vp2[lane + 64]);
        store_split(g_vh, g_vl, ob + lane + 96, vb[lane + 96] + veg * vp2[lane + 96]);
    }
}

// ============================================================================
// flash attention: Q-tile 64, K-tile 32, 4 warps, 3 CTAs/SM, heavy-first.
// ============================================================================
#define KSTR2 136
#define QH_ 0
#define QL_ 8704
#define KH_ 17408
#define KL_ 21760
#define VH_ 26112
#define VL_ 30464
#define KSEG_B 69632            // bytes offset (34816 elems * 2)
#define ATTN3_SMEM (69632 + 256)

__global__ __launch_bounds__(128, 3) void attn_mma(
    const int* __restrict__ seg, const int* __restrict__ bm_ptr)
{
    extern __shared__ __align__(128) __nv_bfloat16 sm2[];
    int* kseg = (int*)((char*)sm2 + KSEG_B);
    const unsigned sb = (unsigned)__cvta_generic_to_shared(sm2);
    const int h   = blockIdx.y;
    const int m0  = ((int)gridDim.x - 1 - (int)blockIdx.x) * 64;  // heavy first
    const int tid = threadIdx.x;
    const int wid = tid >> 5, lane = tid & 31;
    const int bm  = bm_ptr[0];
    const int wr  = wid * 16;

    // stage Q tile hi/lo via cp.async
#pragma unroll
    for (int i = 0; i < 8; i++) {
        int f = tid + i * 128;
        int r = f >> 4, u = f & 15;
        size_t ga = (size_t)(m0 + r) * DIM_ + h * D_ + u * 8;
        cpa16(sb + (unsigned)(QH_ + r * KSTR2 + u * 8) * 2, g_qh + ga);
        cpa16(sb + (unsigned)(QL_ + r * KSTR2 + u * 8) * 2, g_ql + ga);
    }
    CP_COMMIT();

    const int r_ = lane >> 2, c_ = lane & 3;
    const int tq0 = m0 + wr + r_, tq1 = tq0 + 8;
    const int sq0 = seg[tq0], sq1 = seg[tq1];

    float mi0 = -1e30f, mi1 = -1e30f, li0 = 0.f, li1 = 0.f;
    float o[16][4];
#pragma unroll
    for (int t = 0; t < 16; t++)
#pragma unroll
        for (int e = 0; e < 4; e++) o[t][e] = 0.f;

    const unsigned a_addr = sb + (unsigned)(QH_ + (wr + (lane & 15)) * KSTR2 + (lane >> 4) * 8) * 2;
    const int g  = lane >> 3, gl = lane & 7;
    const unsigned kb_addr = sb + (unsigned)(KH_ + ((g >> 1) * 8 + gl) * KSTR2 + (g & 1) * 8) * 2;
    const unsigned vb_addr = sb + (unsigned)(VH_ + ((g & 1) * 8 + gl) * KSTR2 + (g >> 1) * 8) * 2;

    const int qs0 = seg[m0], qs1 = seg[m0 + 63];
    int kb_lo = m0 - bm; if (kb_lo < 0) kb_lo = 0; kb_lo >>= 5;
    const int kb_hi = (m0 >> 5) + 1;        // covers keys up to m0+63

    for (int kb = kb_lo; kb <= kb_hi; kb++) {
        const int s0 = kb * 32;
        if (seg[s0 + 31] < qs0 || seg[s0] > qs1) continue;

        __syncthreads();   // prior readers done before restage
#pragma unroll
        for (int i = 0; i < 4; i++) {
            int f = tid + i * 128;
            int r = f >> 4, u = f & 15;
            int t = s0 + r;
            int ts = ((u >> 2) & 1) ? (t > 0 ? t - 1 : 0) : t;
            size_t gk = (size_t)ts * DIM_ + h * D_ + u * 8;
            size_t gv = (size_t)t  * DIM_ + h * D_ + u * 8;
            cpa16(sb + (unsigned)(KH_ + r * KSTR2 + u * 8) * 2, g_kh + gk);
            cpa16(sb + (unsigned)(KL_ + r * KSTR2 + u * 8) * 2, g_kl + gk);
            cpa16(sb + (unsigned)(VH_ + r * KSTR2 + u * 8) * 2, g_vh + gv);
            cpa16(sb + (unsigned)(VL_ + r * KSTR2 + u * 8) * 2, g_vl + gv);
        }
        CP_COMMIT();
        if (tid < 32) kseg[tid] = seg[s0 + tid];
        CP_WAIT0();
        __syncthreads();

        // ---- S = Q K^T over 32 keys (3-term split) ----
        float s[4][4];
#pragma unroll
        for (int j = 0; j < 4; j++)
#pragma unroll
            for (int e = 0; e < 4; e++) s[j][e] = 0.f;

#pragma unroll
        for (int kk = 0; kk < 8; kk++) {
            unsigned ah[4], al[4];
            ldmx4(ah, a_addr + kk * 32);
            ldmx4(al, a_addr + (QL_ - QH_) * 2 + kk * 32);
#pragma unroll
            for (int jp = 0; jp < 2; jp++) {
                unsigned bh[4], bl[4];
                unsigned ba = kb_addr + (unsigned)(jp * 16 * KSTR2) * 2 + kk * 32;
                ldmx4(bh, ba);
                ldmx4(bl, ba + (KL_ - KH_) * 2);
                mma16816(s[2*jp],   ah, bh[0], bh[1]);
                mma16816(s[2*jp],   al, bh[0], bh[1]);
                mma16816(s[2*jp],   ah, bl[0], bl[1]);
                mma16816(s[2*jp+1], ah, bh[2], bh[3]);
                mma16816(s[2*jp+1], al, bh[2], bh[3]);
                mma16816(s[2*jp+1], ah, bl[2], bl[3]);
            }
        }

        // ---- mask + online softmax ----
        float mx0 = -1e30f, mx1 = -1e30f;
#pragma unroll
        for (int j = 0; j < 4; j++) {
            const int nb = 8 * j + 2 * c_;
            const int tk0 = s0 + nb, tk1 = tk0 + 1;
            const int ka = kseg[nb], kb2 = kseg[nb + 1];
            bool v00 = (tk0 <= tq0) && (tk0 >= tq0 - bm) && (ka  == sq0);
            bool v01 = (tk1 <= tq0) && (tk1 >= tq0 - bm) && (kb2 == sq0);
            bool v10 = (tk0 <= tq1) && (tk0 >= tq1 - bm) && (ka  == sq1);
            bool v11 = (tk1 <= tq1) && (tk1 >= tq1 - bm) && (kb2 == sq1);
            s[j][0] = v00 ? s[j][0] * 0.1f : -1e30f;
            s[j][1] = v01 ? s[j][1] * 0.1f : -1e30f;
            s[j][2] = v10 ? s[j][2] * 0.1f : -1e30f;
            s[j][3] = v11 ? s[j][3] * 0.1f : -1e30f;
            mx0 = fmaxf(mx0, fmaxf(s[j][0], s[j][1]));
            mx1 = fmaxf(mx1, fmaxf(s[j][2], s[j][3]));
        }
        mx0 = fmaxf(mx0, __shfl_xor_sync(0xffffffffu, mx0, 1));
        mx0 = fmaxf(mx0, __shfl_xor_sync(0xffffffffu, mx0, 2));
        mx1 = fmaxf(mx1, __shfl_xor_sync(0xffffffffu, mx1, 1));
        mx1 = fmaxf(mx1, __shfl_xor_sync(0xffffffffu, mx1, 2));

        const float nm0 = fmaxf(mi0, mx0), nm1 = fmaxf(mi1, mx1);
        const float al0 = __expf(mi0 - nm0), al1 = __expf(mi1 - nm1);
        mi0 = nm0; mi1 = nm1;
        float rs0 = 0.f, rs1 = 0.f;
#pragma unroll
        for (int j = 0; j < 4; j++) {
            s[j][0] = __expf(s[j][0] - nm0);
            s[j][1] = __expf(s[j][1] - nm0);
            s[j][2] = __expf(s[j][2] - nm1);
            s[j][3] = __expf(s[j][3] - nm1);
            rs0 += s[j][0] + s[j][1];
            rs1 += s[j][2] + s[j][3];
        }
        rs0 += __shfl_xor_sync(0xffffffffu, rs0, 1);
        rs0 += __shfl_xor_sync(0xffffffffu, rs0, 2);
        rs1 += __shfl_xor_sync(0xffffffffu, rs1, 1);
        rs1 += __shfl_xor_sync(0xffffffffu, rs1, 2);
        li0 = li0 * al0 + rs0;
        li1 = li1 * al1 + rs1;
#pragma unroll
        for (int t = 0; t < 16; t++) {
            o[t][0] *= al0; o[t][1] *= al0;
            o[t][2] *= al1; o[t][3] *= al1;
        }

        // ---- O += P V over 32 keys ----
#pragma unroll
        for (int ss = 0; ss < 2; ss++) {
            unsigned pha[4], pla[4];
            pha[0] = packsplit(s[2*ss][0],   s[2*ss][1],   pla[0]);
            pha[1] = packsplit(s[2*ss][2],   s[2*ss][3],   pla[1]);
            pha[2] = packsplit(s[2*ss+1][0], s[2*ss+1][1], pla[2]);
            pha[3] = packsplit(s[2*ss+1][2], s[2*ss+1][3], pla[3]);
#pragma unroll
            for (int dp = 0; dp < 8; dp++) {
                unsigned bh[4], bl[4];
                unsigned ba = vb_addr + (unsigned)(ss * 16 * KSTR2) * 2 + dp * 32;
                ldmx4t(bh, ba);
                ldmx4t(bl, ba + (VL_ - VH_) * 2);
                mma16816(o[2*dp],   pha, bh[0], bh[1]);
                mma16816(o[2*dp],   pla, bh[0], bh[1]);
                mma16816(o[2*dp],   pha, bl[0], bl[1]);
                mma16816(o[2*dp+1], pha, bh[2], bh[3]);
                mma16816(o[2*dp+1], pla, bh[2], bh[3]);
                mma16816(o[2*dp+1], pha, bl[2], bl[3]);
            }
        }
    }

    // ---- epilogue ----
    const float gg0 = g_gate[tq0 * H_ + h], gg1 = g_gate[tq1 * H_ + h];
    const float i0 = gg0 / li0, i1 = gg1 / li1;
#pragma unroll
    for (int t = 0; t < 16; t++) {
        size_t idx0 = (size_t)tq0 * DIM_ + h * D_ + 8 * t + 2 * c_;
        size_t idx1 = (size_t)tq1 * DIM_ + h * D_ + 8 * t + 2 * c_;
        unsigned lw;
        unsigned hw = packsplit(o[t][0] * i0, o[t][1] * i0, lw);
        *(unsigned*)(g_yh + idx0) = hw;
        *(unsigned*)(g_yl + idx0) = lw;
        hw = packsplit(o[t][2] * i1, o[t][3] * i1, lw);
        *(unsigned*)(g_yh + idx1) = hw;
        *(unsigned*)(g_yl + idx1) = lw;
    }
}

// ---------------------------------------------------------------------------
extern "C" void kernel_launch(void* const* d_in, const int* in_sizes, int n_in,
                              void* d_out, int out_size)
{
    const float* x    = (const float*)d_in[0];
    const float* qkvo = (const float*)d_in[1];
    const float* lam  = (const float*)d_in[2];
    const float* ve   = (const float*)d_in[3];
    const float* agw  = (const float*)d_in[4];
    const float* vgw  = (const float*)d_in[5];
    const float* cosb = (const float*)d_in[6];
    const float* sinb = (const float*)d_in[7];
    const int*   seg  = (const int*)d_in[8];
    const int*   bmp  = (const int*)d_in[9];
    float*       out  = (float*)d_out;

    float *p_qkv;
    __nv_bfloat16 *p_xh, *p_xl, *p_wh, *p_wl, *p_yh, *p_yl;
    cudaGetSymbolAddress((void**)&p_qkv, g_qkv);
    cudaGetSymbolAddress((void**)&p_xh, g_xh);
    cudaGetSymbolAddress((void**)&p_xl, g_xl);
    cudaGetSymbolAddress((void**)&p_wh, g_wh);
    cudaGetSymbolAddress((void**)&p_wl, g_wl);
    cudaGetSymbolAddress((void**)&p_yh, g_yh);
    cudaGetSymbolAddress((void**)&p_yl, g_yl);

    cudaFuncSetAttribute(gemm_bf16s,
                         cudaFuncAttributeMaxDynamicSharedMemorySize, GEMM_SMEM);
    cudaFuncSetAttribute(attn_mma,
                         cudaFuncAttributeMaxDynamicSharedMemorySize, ATTN3_SMEM);

    // 0. one-time splits
    convert_split<<<T_ * DIM_ / 1024, 256>>>((const float4*)x,
                                             (uint2*)p_xh, (uint2*)p_xl,
                                             T_ * DIM_ / 4);
    convert_split<<<4 * DIM_ * DIM_ / 1024, 256>>>((const float4*)qkvo,
                                                   (uint2*)p_wh, (uint2*)p_wl,
                                                   4 * DIM_ * DIM_ / 4);

    // 1. qkv = lam0 * x @ Wqkv^T   [3072 x 3072]
    gemm_bf16s<<<dim3(24, 24), 256, GEMM_SMEM>>>(p_xh, p_xl, p_wh, p_wl,
                                                 p_qkv, 3072, lam, 0);

    // 2. rmsnorm + rotary + gates + ve add -> split planes
    postproc_kernel<<<T_, 256>>>(x, ve, vgw, agw, cosb, sinb);

    // 3. attention (K-tile 32, 3 CTAs/SM; k-shift fused; heavy-first)
    attn_mma<<<dim3(T_ / 64, H_), 128, ATTN3_SMEM>>>(seg, bmp);

    // 4. out = lam1 * y @ Wo^T   [3072 x 1024]
    gemm_bf16s<<<dim3(8, 24), 256, GEMM_SMEM>>>(
        p_yh, p_yl, p_wh + (size_t)3 * DIM_ * DIM_, p_wl + (size_t)3 * DIM_ * DIM_,
        out, 1024, lam, 1);
}

// round 13
// speedup vs baseline: 1.6140x; 1.1349x over previous
#include <cuda_runtime.h>
#include <cuda_bf16.h>
#include <cuda_fp16.h>
#include <math.h>
#include <stdint.h>

#define T_   3072
#define DIM_ 1024
#define H_   8
#define D_   128

// ---------------- scratch (device globals: no allocation allowed) ----------
__device__ float g_qkv[(size_t)T_ * 3 * DIM_];
__device__ float g_gate[T_ * H_];
__device__ __nv_bfloat16 g_xh[(size_t)T_ * DIM_], g_xl[(size_t)T_ * DIM_];
__device__ __nv_bfloat16 g_wh[(size_t)4 * DIM_ * DIM_], g_wl[(size_t)4 * DIM_ * DIM_];
__device__ __half g_q16h[(size_t)T_ * DIM_], g_q16l[(size_t)T_ * DIM_];
__device__ __half g_k16[(size_t)T_ * DIM_];
__device__ __half g_v16[(size_t)T_ * DIM_];
__device__ __nv_bfloat16 g_yh[(size_t)T_ * DIM_], g_yl[(size_t)T_ * DIM_];

// ---------------- helpers ---------------------------------------------------
__device__ __forceinline__ void cpa16(unsigned dst, const void* src) {
    asm volatile("cp.async.cg.shared.global [%0],[%1],16;" :: "r"(dst), "l"(src));
}
#define CP_COMMIT() asm volatile("cp.async.commit_group;" ::: "memory")
#define CP_WAIT0()  asm volatile("cp.async.wait_group 0;" ::: "memory")

__device__ __forceinline__ void ldmx4(unsigned r[4], unsigned addr) {
    asm volatile("ldmatrix.sync.aligned.m8n8.x4.shared.b16 {%0,%1,%2,%3},[%4];"
                 : "=r"(r[0]), "=r"(r[1]), "=r"(r[2]), "=r"(r[3]) : "r"(addr));
}
__device__ __forceinline__ void ldmx4t(unsigned r[4], unsigned addr) {
    asm volatile("ldmatrix.sync.aligned.m8n8.x4.trans.shared.b16 {%0,%1,%2,%3},[%4];"
                 : "=r"(r[0]), "=r"(r[1]), "=r"(r[2]), "=r"(r[3]) : "r"(addr));
}
__device__ __forceinline__ void mma16816(float c[4], const unsigned a[4],
                                         const unsigned b0, const unsigned b1) {
    asm volatile("mma.sync.aligned.m16n8k16.row.col.f32.bf16.bf16.f32 "
                 "{%0,%1,%2,%3},{%4,%5,%6,%7},{%8,%9},{%0,%1,%2,%3};"
                 : "+f"(c[0]), "+f"(c[1]), "+f"(c[2]), "+f"(c[3])
                 : "r"(a[0]), "r"(a[1]), "r"(a[2]), "r"(a[3]), "r"(b0), "r"(b1));
}
__device__ __forceinline__ void mma16816h(float c[4], const unsigned a[4],
                                          const unsigned b0, const unsigned b1) {
    asm volatile("mma.sync.aligned.m16n8k16.row.col.f32.f16.f16.f32 "
                 "{%0,%1,%2,%3},{%4,%5,%6,%7},{%8,%9},{%0,%1,%2,%3};"
                 : "+f"(c[0]), "+f"(c[1]), "+f"(c[2]), "+f"(c[3])
                 : "r"(a[0]), "r"(a[1]), "r"(a[2]), "r"(a[3]), "r"(b0), "r"(b1));
}
__device__ __forceinline__ void split4(float4 v, uint2& h, uint2& l) {
    __nv_bfloat16 hx = __float2bfloat16(v.x), hy = __float2bfloat16(v.y);
    __nv_bfloat16 hz = __float2bfloat16(v.z), hw = __float2bfloat16(v.w);
    __nv_bfloat16 lx = __float2bfloat16(v.x - __bfloat162float(hx));
    __nv_bfloat16 ly = __float2bfloat16(v.y - __bfloat162float(hy));
    __nv_bfloat16 lz = __float2bfloat16(v.z - __bfloat162float(hz));
    __nv_bfloat16 lw = __float2bfloat16(v.w - __bfloat162float(hw));
    h.x = (unsigned)__bfloat16_as_ushort(hx) | ((unsigned)__bfloat16_as_ushort(hy) << 16);
    h.y = (unsigned)__bfloat16_as_ushort(hz) | ((unsigned)__bfloat16_as_ushort(hw) << 16);
    l.x = (unsigned)__bfloat16_as_ushort(lx) | ((unsigned)__bfloat16_as_ushort(ly) << 16);
    l.y = (unsigned)__bfloat16_as_ushort(lz) | ((unsigned)__bfloat16_as_ushort(lw) << 16);
}
__device__ __forceinline__ unsigned packsplit(float p0, float p1, unsigned& lo) {
    __nv_bfloat16 h0 = __float2bfloat16(p0), h1 = __float2bfloat16(p1);
    __nv_bfloat16 l0 = __float2bfloat16(p0 - __bfloat162float(h0));
    __nv_bfloat16 l1 = __float2bfloat16(p1 - __bfloat162float(h1));
    lo = (unsigned)__bfloat16_as_ushort(l0) | ((unsigned)__bfloat16_as_ushort(l1) << 16);
    return (unsigned)__bfloat16_as_ushort(h0) | ((unsigned)__bfloat16_as_ushort(h1) << 16);
}
__device__ __forceinline__ unsigned packsplit_h(float p0, float p1, unsigned& lo) {
    __half h0 = __float2half_rn(p0), h1 = __float2half_rn(p1);
    __half l0 = __float2half_rn(p0 - __half2float(h0));
    __half l1 = __float2half_rn(p1 - __half2float(h1));
    lo = (unsigned)__half_as_ushort(l0) | ((unsigned)__half_as_ushort(l1) << 16);
    return (unsigned)__half_as_ushort(h0) | ((unsigned)__half_as_ushort(h1) << 16);
}
__device__ __forceinline__ void store_split_h(__half* ph, __half* pl,
                                              size_t i, float v) {
    __half h = __float2half_rn(v);
    ph[i] = h;
    pl[i] = __float2half_rn(v - __half2float(h));
}

// ---------------- one-time fp32 -> (hi,lo) bf16 conversion ------------------
__global__ __launch_bounds__(256) void convert_split(
    const float4* __restrict__ src, uint2* __restrict__ dh,
    uint2* __restrict__ dl, int n4)
{
    int i = blockIdx.x * 256 + threadIdx.x;
    if (i < n4) {
        uint2 h, l;
        split4(src[i], h, l);
        dh[i] = h; dl[i] = l;
    }
}

// ============================================================================
// bf16-split mma.sync GEMM, cp.async staging; 2 CTAs/SM (R9 WIN, unchanged)
// ============================================================================
#define ROWB  80
#define AHI_  0
#define ALO_  10240
#define BHI_  20480
#define BLO_  30720
#define BUFB  40960
#define GEMM_SMEM (2 * BUFB)

__global__ __launch_bounds__(256, 2) void gemm_bf16s(
    const __nv_bfloat16* __restrict__ Ah, const __nv_bfloat16* __restrict__ Al,
    const __nv_bfloat16* __restrict__ Bh, const __nv_bfloat16* __restrict__ Bl,
    float* __restrict__ C, int N, const float* __restrict__ lam, int lidx)
{
    extern __shared__ __align__(128) char smem[];
    const unsigned sb = (unsigned)__cvta_generic_to_shared(smem);
    const int tid  = threadIdx.x;
    const int wid  = tid >> 5;
    const int lane = tid & 31;
    const int m0 = blockIdx.y * 128;
    const int n0 = blockIdx.x * 128;
    const int wm0 = (wid & 1) * 64;
    const int wn0 = (wid >> 1) * 32;

    float acc[4][4][4];
#pragma unroll
    for (int mi = 0; mi < 4; mi++)
#pragma unroll
        for (int ni = 0; ni < 4; ni++)
#pragma unroll
            for (int e = 0; e < 4; e++) acc[mi][ni][e] = 0.f;

    auto stage = [&](int c, int buf) {
        const int kc = c * 32;
        const unsigned bb = sb + buf * BUFB;
#pragma unroll
        for (int i = 0; i < 2; i++) {
            int f = tid + i * 256;
            int row = f >> 2, q = f & 3;
            size_t ga = (size_t)(m0 + row) * 1024 + kc + q * 8;
            size_t gb = (size_t)(n0 + row) * 1024 + kc + q * 8;
            unsigned so = (unsigned)(row * ROWB + q * 16);
            cpa16(bb + AHI_ + so, Ah + ga);
            cpa16(bb + ALO_ + so, Al + ga);
            cpa16(bb + BHI_ + so, Bh + gb);
            cpa16(bb + BLO_ + so, Bl + gb);
        }
        CP_COMMIT();
    };

    const int a_row = lane & 15;
    const int a_kb  = (lane >> 4) * 16;
    const int b_nrl = ((lane >> 4) << 3) + (lane & 7);
    const int b_kb  = ((lane >> 3) & 1) * 16;

    stage(0, 0);

    for (int c = 0; c < 32; c++) {
        const int buf = c & 1;
        CP_WAIT0();
        __syncthreads();
        if (c + 1 < 32) stage(c + 1, buf ^ 1);

        const unsigned base = sb + buf * BUFB;
#pragma unroll
        for (int ks = 0; ks < 2; ks++) {
            unsigned ah[4][4], al[4][4], bh[4][2], bl[4][2];
#pragma unroll
            for (int mi = 0; mi < 4; mi++) {
                unsigned ad = base + AHI_ +
                    (unsigned)((wm0 + mi * 16 + a_row) * ROWB + ks * 32 + a_kb);
                ldmx4(ah[mi], ad);
                ldmx4(al[mi], ad + (ALO_ - AHI_));
            }
#pragma unroll
            for (int p = 0; p < 2; p++) {
                unsigned bd = base + BHI_ +
                    (unsigned)((wn0 + p * 16 + b_nrl) * ROWB + ks * 32 + b_kb);
                unsigned r[4];
                ldmx4(r, bd);
                bh[2*p][0] = r[0]; bh[2*p][1] = r[1];
                bh[2*p+1][0] = r[2]; bh[2*p+1][1] = r[3];
                ldmx4(r, bd + (BLO_ - BHI_));
                bl[2*p][0] = r[0]; bl[2*p][1] = r[1];
                bl[2*p+1][0] = r[2]; bl[2*p+1][1] = r[3];
            }
#pragma unroll
            for (int mi = 0; mi < 4; mi++)
#pragma unroll
                for (int ni = 0; ni < 4; ni++) {
                    mma16816(acc[mi][ni], ah[mi], bh[ni][0], bh[ni][1]);
                    mma16816(acc[mi][ni], al[mi], bh[ni][0], bh[ni][1]);
                    mma16816(acc[mi][ni], ah[mi], bl[ni][0], bl[ni][1]);
                }
        }
    }

    const float alpha = lam[lidx];
    const int r  = lane >> 2;
    const int cc = (lane & 3) * 2;
#pragma unroll
    for (int mi = 0; mi < 4; mi++)
#pragma unroll
        for (int ni = 0; ni < 4; ni++) {
            const int row = m0 + wm0 + mi * 16 + r;
            const int col = n0 + wn0 + ni * 8 + cc;
            float2 w0; w0.x = alpha * acc[mi][ni][0]; w0.y = alpha * acc[mi][ni][1];
            float2 w1; w1.x = alpha * acc[mi][ni][2]; w1.y = alpha * acc[mi][ni][3];
            *(float2*)(C + (size_t)row * N + col) = w0;
            *(float2*)(C + (size_t)(row + 8) * N + col) = w1;
        }
}

// ------------- postprocess: rmsnorm + rotary + gates + ve; fp16 out --------
__global__ __launch_bounds__(256) void postproc_kernel(
    const float* __restrict__ x, const float* __restrict__ ve,
    const float* __restrict__ ve_gate_w, const float* __restrict__ attn_gate_w,
    const float* __restrict__ cosb, const float* __restrict__ sinb)
{
    const int t    = blockIdx.x;
    const int w    = threadIdx.x >> 5;
    const int lane = threadIdx.x & 31;
    const float* base = g_qkv + (size_t)t * (3 * DIM_);
    const size_t ob = (size_t)t * DIM_ + w * D_;

    const float c0 = cosb[t * 64 + lane],      s0 = sinb[t * 64 + lane];
    const float c1 = cosb[t * 64 + lane + 32], s1 = sinb[t * 64 + lane + 32];

    {
        const float* qb = base + w * D_;
        float a0 = qb[lane], a1 = qb[lane + 32], a2 = qb[lane + 64], a3 = qb[lane + 96];
        float ss = a0*a0 + a1*a1 + a2*a2 + a3*a3;
#pragma unroll
        for (int off = 16; off; off >>= 1) ss += __shfl_xor_sync(0xffffffffu, ss, off);
        float r = rsqrtf(ss * (1.0f / 128.0f) + 1e-6f);
        a0 *= r; a1 *= r; a2 *= r; a3 *= r;
        store_split_h(g_q16h, g_q16l, ob + lane,       a0 * c0 + a2 * s0);
        store_split_h(g_q16h, g_q16l, ob + lane + 32,  a1 * c1 + a3 * s1);
        store_split_h(g_q16h, g_q16l, ob + lane + 64, -a0 * s0 + a2 * c0);
        store_split_h(g_q16h, g_q16l, ob + lane + 96, -a1 * s1 + a3 * c1);
    }
    {
        const float* kb = base + DIM_ + w * D_;
        float a0 = kb[lane], a1 = kb[lane + 32], a2 = kb[lane + 64], a3 = kb[lane + 96];
        float ss = a0*a0 + a1*a1 + a2*a2 + a3*a3;
#pragma unroll
        for (int off = 16; off; off >>= 1) ss += __shfl_xor_sync(0xffffffffu, ss, off);
        float r = rsqrtf(ss * (1.0f / 128.0f) + 1e-6f);
        a0 *= r; a1 *= r; a2 *= r; a3 *= r;
        g_k16[ob + lane]      = __float2half_rn( a0 * c0 + a2 * s0);
        g_k16[ob + lane + 32] = __float2half_rn( a1 * c1 + a3 * s1);
        g_k16[ob + lane + 64] = __float2half_rn(-a0 * s0 + a2 * c0);
        g_k16[ob + lane + 96] = __float2half_rn(-a1 * s1 + a3 * c1);
    }
    float xv = (lane < 16) ? x[(size_t)t * DIM_ + lane] : 0.f;
    float dv = (lane < 16) ? xv * ve_gate_w[w * 16 + lane]   : 0.f;
    float da = (lane < 16) ? xv * attn_gate_w[w * 16 + lane] : 0.f;
#pragma unroll
    for (int off = 16; off; off >>= 1) {
        dv += __shfl_xor_sync(0xffffffffu, dv, off);
        da += __shfl_xor_sync(0xffffffffu, da, off);
    }
    const float veg = 2.0f / (1.0f + __expf(-dv));
    if (lane == 0) g_gate[t * H_ + w] = 1.0f / (1.0f + __expf(-da));
    {
        const float* vb  = base + 2 * DIM_ + w * D_;
        const float* vp2 = ve + ob;
        g_v16[ob + lane]      = __float2half_rn(vb[lane]      + veg * vp2[lane]);
        g_v16[ob + lane + 32] = __float2half_rn(vb[lane + 32] + veg * vp2[lane + 32]);
        g_v16[ob + lane + 64] = __float2half_rn(vb[lane + 64] + veg * vp2[lane + 64]);
        g_v16[ob + lane + 96] = __float2half_rn(vb[lane + 96] + veg * vp2[lane + 96]);
    }
}

// ============================================================================
// flash attention: fp16 asymmetric split (Q 2-term, K/V single), 3 CTAs/SM.
// ============================================================================
#define KSTR2 136
#define QH_ 0
#define QL_ 8704
#define KH_ 17408
#define VH_ 26112
#define KSEG_B 69632
#define ATTN2_SMEM (69632 + 256)

__global__ __launch_bounds__(128, 3) void attn_mma(
    const int* __restrict__ seg, const int* __restrict__ bm_ptr)
{
    extern __shared__ __align__(128) __half sm2[];
    int* kseg = (int*)((char*)sm2 + KSEG_B);
    const unsigned sb = (unsigned)__cvta_generic_to_shared(sm2);
    const int h   = blockIdx.y;
    const int m0  = ((int)gridDim.x - 1 - (int)blockIdx.x) * 64;  // heavy first
    const int tid = threadIdx.x;
    const int wid = tid >> 5, lane = tid & 31;
    const int bm  = bm_ptr[0];
    const int wr  = wid * 16;

    // stage Q tile hi/lo via cp.async
#pragma unroll
    for (int i = 0; i < 8; i++) {
        int f = tid + i * 128;
        int r = f >> 4, u = f & 15;
        size_t ga = (size_t)(m0 + r) * DIM_ + h * D_ + u * 8;
        cpa16(sb + (unsigned)(QH_ + r * KSTR2 + u * 8) * 2, g_q16h + ga);
        cpa16(sb + (unsigned)(QL_ + r * KSTR2 + u * 8) * 2, g_q16l + ga);
    }
    CP_COMMIT();

    const int r_ = lane >> 2, c_ = lane & 3;
    const int tq0 = m0 + wr + r_, tq1 = tq0 + 8;
    const int sq0 = seg[tq0], sq1 = seg[tq1];

    float mi0 = -1e30f, mi1 = -1e30f, li0 = 0.f, li1 = 0.f;
    float o[16][4];
#pragma unroll
    for (int t = 0; t < 16; t++)
#pragma unroll
        for (int e = 0; e < 4; e++) o[t][e] = 0.f;

    const unsigned a_addr = sb + (unsigned)(QH_ + (wr + (lane & 15)) * KSTR2 + (lane >> 4) * 8) * 2;
    const int g  = lane >> 3, gl = lane & 7;
    const unsigned kb_addr = sb + (unsigned)(KH_ + ((g >> 1) * 8 + gl) * KSTR2 + (g & 1) * 8) * 2;
    const unsigned vb_addr = sb + (unsigned)(VH_ + ((g & 1) * 8 + gl) * KSTR2 + (g >> 1) * 8) * 2;

    const int qs0 = seg[m0], qs1 = seg[m0 + 63];
    int kb_lo = m0 - bm; if (kb_lo < 0) kb_lo = 0; kb_lo >>= 6;
    const int kb_hi = m0 >> 6;

    for (int kb = kb_lo; kb <= kb_hi; kb++) {
        const int s0 = kb * 64;
        if (seg[s0 + 63] < qs0 || seg[s0] > qs1) continue;

        __syncthreads();   // prior readers done before restage
#pragma unroll
        for (int i = 0; i < 8; i++) {
            int f = tid + i * 128;
            int r = f >> 4, u = f & 15;
            int t = s0 + r;
            int ts = ((u >> 2) & 1) ? (t > 0 ? t - 1 : 0) : t;
            size_t gk = (size_t)ts * DIM_ + h * D_ + u * 8;
            size_t gv = (size_t)t  * DIM_ + h * D_ + u * 8;
            cpa16(sb + (unsigned)(KH_ + r * KSTR2 + u * 8) * 2, g_k16 + gk);
            cpa16(sb + (unsigned)(VH_ + r * KSTR2 + u * 8) * 2, g_v16 + gv);
        }
        CP_COMMIT();
        if (tid < 64) kseg[tid] = seg[s0 + tid];
        CP_WAIT0();
        __syncthreads();

        // ---- S = (Qh+Ql) Kh^T (fp16, 2-term) ----
        float s[8][4];
#pragma unroll
        for (int j = 0; j < 8; j++)
#pragma unroll
            for (int e = 0; e < 4; e++) s[j][e] = 0.f;

#pragma unroll
        for (int kk = 0; kk < 8; kk++) {
            unsigned ah[4], al[4];
            ldmx4(ah, a_addr + kk * 32);
            ldmx4(al, a_addr + (QL_ - QH_) * 2 + kk * 32);
#pragma unroll
            for (int jp = 0; jp < 4; jp++) {
                unsigned bh[4];
                ldmx4(bh, kb_addr + (unsigned)(jp * 16 * KSTR2) * 2 + kk * 32);
                mma16816h(s[2*jp],   ah, bh[0], bh[1]);
                mma16816h(s[2*jp],   al, bh[0], bh[1]);
                mma16816h(s[2*jp+1], ah, bh[2], bh[3]);
                mma16816h(s[2*jp+1], al, bh[2], bh[3]);
            }
        }

        // ---- mask + online softmax ----
        float mx0 = -1e30f, mx1 = -1e30f;
#pragma unroll
        for (int j = 0; j < 8; j++) {
            const int nb = 8 * j + 2 * c_;
            const int tk0 = s0 + nb, tk1 = tk0 + 1;
            const int ka = kseg[nb], kb2 = kseg[nb + 1];
            bool v00 = (tk0 <= tq0) && (tk0 >= tq0 - bm) && (ka  == sq0);
            bool v01 = (tk1 <= tq0) && (tk1 >= tq0 - bm) && (kb2 == sq0);
            bool v10 = (tk0 <= tq1) && (tk0 >= tq1 - bm) && (ka  == sq1);
            bool v11 = (tk1 <= tq1) && (tk1 >= tq1 - bm) && (kb2 == sq1);
            s[j][0] = v00 ? s[j][0] * 0.1f : -1e30f;
            s[j][1] = v01 ? s[j][1] * 0.1f : -1e30f;
            s[j][2] = v10 ? s[j][2] * 0.1f : -1e30f;
            s[j][3] = v11 ? s[j][3] * 0.1f : -1e30f;
            mx0 = fmaxf(mx0, fmaxf(s[j][0], s[j][1]));
            mx1 = fmaxf(mx1, fmaxf(s[j][2], s[j][3]));
        }
        mx0 = fmaxf(mx0, __shfl_xor_sync(0xffffffffu, mx0, 1));
        mx0 = fmaxf(mx0, __shfl_xor_sync(0xffffffffu, mx0, 2));
        mx1 = fmaxf(mx1, __shfl_xor_sync(0xffffffffu, mx1, 1));
        mx1 = fmaxf(mx1, __shfl_xor_sync(0xffffffffu, mx1, 2));

        const float nm0 = fmaxf(mi0, mx0), nm1 = fmaxf(mi1, mx1);
        const float al0 = __expf(mi0 - nm0), al1 = __expf(mi1 - nm1);
        mi0 = nm0; mi1 = nm1;
        float rs0 = 0.f, rs1 = 0.f;
#pragma unroll
        for (int j = 0; j < 8; j++) {
            s[j][0] = __expf(s[j][0] - nm0);
            s[j][1] = __expf(s[j][1] - nm0);
            s[j][2] = __expf(s[j][2] - nm1);
            s[j][3] = __expf(s[j][3] - nm1);
            rs0 += s[j][0] + s[j][1];
            rs1 += s[j][2] + s[j][3];
        }
        rs0 += __shfl_xor_sync(0xffffffffu, rs0, 1);
        rs0 += __shfl_xor_sync(0xffffffffu, rs0, 2);
        rs1 += __shfl_xor_sync(0xffffffffu, rs1, 1);
        rs1 += __shfl_xor_sync(0xffffffffu, rs1, 2);
        li0 = li0 * al0 + rs0;
        li1 = li1 * al1 + rs1;
#pragma unroll
        for (int t = 0; t < 16; t++) {
            o[t][0] *= al0; o[t][1] *= al0;
            o[t][2] *= al1; o[t][3] *= al1;
        }

        // ---- O += (Ph+Pl) Vh (fp16, 2-term) ----
#pragma unroll
        for (int ss = 0; ss < 4; ss++) {
            unsigned pha[4], pla[4];
            pha[0] = packsplit_h(s[2*ss][0],   s[2*ss][1],   pla[0]);
            pha[1] = packsplit_h(s[2*ss][2],   s[2*ss][3],   pla[1]);
            pha[2] = packsplit_h(s[2*ss+1][0], s[2*ss+1][1], pla[2]);
            pha[3] = packsplit_h(s[2*ss+1][2], s[2*ss+1][3], pla[3]);
#pragma unroll
            for (int dp = 0; dp < 8; dp++) {
                unsigned bh[4];
                ldmx4t(bh, vb_addr + (unsigned)(ss * 16 * KSTR2) * 2 + dp * 32);
                mma16816h(o[2*dp],   pha, bh[0], bh[1]);
                mma16816h(o[2*dp],   pla, bh[0], bh[1]);
                mma16816h(o[2*dp+1], pha, bh[2], bh[3]);
                mma16816h(o[2*dp+1], pla, bh[2], bh[3]);
            }
        }
    }

    // ---- epilogue: normalize, gate, store y as bf16 hi/lo planes ----
    const float gg0 = g_gate[tq0 * H_ + h], gg1 = g_gate[tq1 * H_ + h];
    const float i0 = gg0 / li0, i1 = gg1 / li1;
#pragma unroll
    for (int t = 0; t < 16; t++) {
        size_t idx0 = (size_t)tq0 * DIM_ + h * D_ + 8 * t + 2 * c_;
        size_t idx1 = (size_t)tq1 * DIM_ + h * D_ + 8 * t + 2 * c_;
        unsigned lw;
        unsigned hw = packsplit(o[t][0] * i0, o[t][1] * i0, lw);
        *(unsigned*)(g_yh + idx0) = hw;
        *(unsigned*)(g_yl + idx0) = lw;
        hw = packsplit(o[t][2] * i1, o[t][3] * i1, lw);
        *(unsigned*)(g_yh + idx1) = hw;
        *(unsigned*)(g_yl + idx1) = lw;
    }
}

// ---------------------------------------------------------------------------
extern "C" void kernel_launch(void* const* d_in, const int* in_sizes, int n_in,
                              void* d_out, int out_size)
{
    const float* x    = (const float*)d_in[0];
    const float* qkvo = (const float*)d_in[1];
    const float* lam  = (const float*)d_in[2];
    const float* ve   = (const float*)d_in[3];
    const float* agw  = (const float*)d_in[4];
    const float* vgw  = (const float*)d_in[5];
    const float* cosb = (const float*)d_in[6];
    const float* sinb = (const float*)d_in[7];
    const int*   seg  = (const int*)d_in[8];
    const int*   bmp  = (const int*)d_in[9];
    float*       out  = (float*)d_out;

    float *p_qkv;
    __nv_bfloat16 *p_xh, *p_xl, *p_wh, *p_wl, *p_yh, *p_yl;
    cudaGetSymbolAddress((void**)&p_qkv, g_qkv);
    cudaGetSymbolAddress((void**)&p_xh, g_xh);
    cudaGetSymbolAddress((void**)&p_xl, g_xl);
    cudaGetSymbolAddress((void**)&p_wh, g_wh);
    cudaGetSymbolAddress((void**)&p_wl, g_wl);
    cudaGetSymbolAddress((void**)&p_yh, g_yh);
    cudaGetSymbolAddress((void**)&p_yl, g_yl);

    cudaFuncSetAttribute(gemm_bf16s,
                         cudaFuncAttributeMaxDynamicSharedMemorySize, GEMM_SMEM);
    cudaFuncSetAttribute(attn_mma,
                         cudaFuncAttributeMaxDynamicSharedMemorySize, ATTN2_SMEM);

    // 0. one-time splits
    convert_split<<<T_ * DIM_ / 1024, 256>>>((const float4*)x,
                                             (uint2*)p_xh, (uint2*)p_xl,
                                             T_ * DIM_ / 4);
    convert_split<<<4 * DIM_ * DIM_ / 1024, 256>>>((const float4*)qkvo,
                                                   (uint2*)p_wh, (uint2*)p_wl,
                                                   4 * DIM_ * DIM_ / 4);

    // 1. qkv = lam0 * x @ Wqkv^T   [3072 x 3072]
    gemm_bf16s<<<dim3(24, 24), 256, GEMM_SMEM>>>(p_xh, p_xl, p_wh, p_wl,
                                                 p_qkv, 3072, lam, 0);

    // 2. rmsnorm + rotary + gates + ve add -> fp16 planes
    postproc_kernel<<<T_, 256>>>(x, ve, vgw, agw, cosb, sinb);

    // 3. attention (fp16 2-term; 3 CTAs/SM; k-shift fused; heavy-first)
    attn_mma<<<dim3(T_ / 64, H_), 128, ATTN2_SMEM>>>(seg, bmp);

    // 4. out = lam1 * y @ Wo^T   [3072 x 1024]
    gemm_bf16s<<<dim3(8, 24), 256, GEMM_SMEM>>>(
        p_yh, p_yl, p_wh + (size_t)3 * DIM_ * DIM_, p_wl + (size_t)3 * DIM_ * DIM_,
        out, 1024, lam, 1);
}

// round 15
// speedup vs baseline: 1.7500x; 1.0843x over previous
#include <cuda_runtime.h>
#include <cuda_bf16.h>
#include <cuda_fp16.h>
#include <math.h>
#include <stdint.h>

#define T_   3072
#define DIM_ 1024
#define H_   8
#define D_   128

// ---------------- scratch (device globals: no allocation allowed) ----------
__device__ float g_qkv[(size_t)T_ * 3 * DIM_];
__device__ float g_gate[T_ * H_];
__device__ __nv_bfloat16 g_xh[(size_t)T_ * DIM_], g_xl[(size_t)T_ * DIM_];
__device__ __nv_bfloat16 g_wh[(size_t)4 * DIM_ * DIM_], g_wl[(size_t)4 * DIM_ * DIM_];
__device__ __half g_q16[(size_t)T_ * DIM_];
__device__ __half g_k16[(size_t)T_ * DIM_];
__device__ __half g_v16[(size_t)T_ * DIM_];
__device__ __nv_bfloat16 g_yh[(size_t)T_ * DIM_], g_yl[(size_t)T_ * DIM_];

// ---------------- helpers ---------------------------------------------------
__device__ __forceinline__ void cpa16(unsigned dst, const void* src) {
    asm volatile("cp.async.cg.shared.global [%0],[%1],16;" :: "r"(dst), "l"(src));
}
#define CP_COMMIT() asm volatile("cp.async.commit_group;" ::: "memory")
#define CP_WAIT0()  asm volatile("cp.async.wait_group 0;" ::: "memory")

__device__ __forceinline__ void ldmx4(unsigned r[4], unsigned addr) {
    asm volatile("ldmatrix.sync.aligned.m8n8.x4.shared.b16 {%0,%1,%2,%3},[%4];"
                 : "=r"(r[0]), "=r"(r[1]), "=r"(r[2]), "=r"(r[3]) : "r"(addr));
}
__device__ __forceinline__ void ldmx4t(unsigned r[4], unsigned addr) {
    asm volatile("ldmatrix.sync.aligned.m8n8.x4.trans.shared.b16 {%0,%1,%2,%3},[%4];"
                 : "=r"(r[0]), "=r"(r[1]), "=r"(r[2]), "=r"(r[3]) : "r"(addr));
}
__device__ __forceinline__ void mma16816(float c[4], const unsigned a[4],
                                         const unsigned b0, const unsigned b1) {
    asm volatile("mma.sync.aligned.m16n8k16.row.col.f32.bf16.bf16.f32 "
                 "{%0,%1,%2,%3},{%4,%5,%6,%7},{%8,%9},{%0,%1,%2,%3};"
                 : "+f"(c[0]), "+f"(c[1]), "+f"(c[2]), "+f"(c[3])
                 : "r"(a[0]), "r"(a[1]), "r"(a[2]), "r"(a[3]), "r"(b0), "r"(b1));
}
__device__ __forceinline__ void mma16816h(float c[4], const unsigned a[4],
                                          const unsigned b0, const unsigned b1) {
    asm volatile("mma.sync.aligned.m16n8k16.row.col.f32.f16.f16.f32 "
                 "{%0,%1,%2,%3},{%4,%5,%6,%7},{%8,%9},{%0,%1,%2,%3};"
                 : "+f"(c[0]), "+f"(c[1]), "+f"(c[2]), "+f"(c[3])
                 : "r"(a[0]), "r"(a[1]), "r"(a[2]), "r"(a[3]), "r"(b0), "r"(b1));
}
__device__ __forceinline__ void split4(float4 v, uint2& h, uint2& l) {
    __nv_bfloat16 hx = __float2bfloat16(v.x), hy = __float2bfloat16(v.y);
    __nv_bfloat16 hz = __float2bfloat16(v.z), hw = __float2bfloat16(v.w);
    __nv_bfloat16 lx = __float2bfloat16(v.x - __bfloat162float(hx));
    __nv_bfloat16 ly = __float2bfloat16(v.y - __bfloat162float(hy));
    __nv_bfloat16 lz = __float2bfloat16(v.z - __bfloat162float(hz));
    __nv_bfloat16 lw = __float2bfloat16(v.w - __bfloat162float(hw));
    h.x = (unsigned)__bfloat16_as_ushort(hx) | ((unsigned)__bfloat16_as_ushort(hy) << 16);
    h.y = (unsigned)__bfloat16_as_ushort(hz) | ((unsigned)__bfloat16_as_ushort(hw) << 16);
    l.x = (unsigned)__bfloat16_as_ushort(lx) | ((unsigned)__bfloat16_as_ushort(ly) << 16);
    l.y = (unsigned)__bfloat16_as_ushort(lz) | ((unsigned)__bfloat16_as_ushort(lw) << 16);
}
__device__ __forceinline__ unsigned packsplit(float p0, float p1, unsigned& lo) {
    __nv_bfloat16 h0 = __float2bfloat16(p0), h1 = __float2bfloat16(p1);
    __nv_bfloat16 l0 = __float2bfloat16(p0 - __bfloat162float(h0));
    __nv_bfloat16 l1 = __float2bfloat16(p1 - __bfloat162float(h1));
    lo = (unsigned)__bfloat16_as_ushort(l0) | ((unsigned)__bfloat16_as_ushort(l1) << 16);
    return (unsigned)__bfloat16_as_ushort(h0) | ((unsigned)__bfloat16_as_ushort(h1) << 16);
}
__device__ __forceinline__ unsigned pack2h(float p0, float p1) {
    __half h0 = __float2half_rn(p0), h1 = __float2half_rn(p1);
    return (unsigned)__half_as_ushort(h0) | ((unsigned)__half_as_ushort(h1) << 16);
}

// ---------------- one-time fp32 -> (hi,lo) bf16 conversion ------------------
__global__ __launch_bounds__(256) void convert_split(
    const float4* __restrict__ src, uint2* __restrict__ dh,
    uint2* __restrict__ dl, int n4)
{
    int i = blockIdx.x * 256 + threadIdx.x;
    if (i < n4) {
        uint2 h, l;
        split4(src[i], h, l);
        dh[i] = h; dl[i] = l;
    }
}

// ============================================================================
// bf16-split mma.sync GEMM, cp.async staging; 2 CTAs/SM (R9 WIN, unchanged)
// ============================================================================
#define ROWB  80
#define AHI_  0
#define ALO_  10240
#define BHI_  20480
#define BLO_  30720
#define BUFB  40960
#define GEMM_SMEM (2 * BUFB)

__global__ __launch_bounds__(256, 2) void gemm_bf16s(
    const __nv_bfloat16* __restrict__ Ah, const __nv_bfloat16* __restrict__ Al,
    const __nv_bfloat16* __restrict__ Bh, const __nv_bfloat16* __restrict__ Bl,
    float* __restrict__ C, int N, const float* __restrict__ lam, int lidx)
{
    extern __shared__ __align__(128) char smem[];
    const unsigned sb = (unsigned)__cvta_generic_to_shared(smem);
    const int tid  = threadIdx.x;
    const int wid  = tid >> 5;
    const int lane = tid & 31;
    const int m0 = blockIdx.y * 128;
    const int n0 = blockIdx.x * 128;
    const int wm0 = (wid & 1) * 64;
    const int wn0 = (wid >> 1) * 32;

    float acc[4][4][4];
#pragma unroll
    for (int mi = 0; mi < 4; mi++)
#pragma unroll
        for (int ni = 0; ni < 4; ni++)
#pragma unroll
            for (int e = 0; e < 4; e++) acc[mi][ni][e] = 0.f;

    auto stage = [&](int c, int buf) {
        const int kc = c * 32;
        const unsigned bb = sb + buf * BUFB;
#pragma unroll
        for (int i = 0; i < 2; i++) {
            int f = tid + i * 256;
            int row = f >> 2, q = f & 3;
            size_t ga = (size_t)(m0 + row) * 1024 + kc + q * 8;
            size_t gb = (size_t)(n0 + row) * 1024 + kc + q * 8;
            unsigned so = (unsigned)(row * ROWB + q * 16);
            cpa16(bb + AHI_ + so, Ah + ga);
            cpa16(bb + ALO_ + so, Al + ga);
            cpa16(bb + BHI_ + so, Bh + gb);
            cpa16(bb + BLO_ + so, Bl + gb);
        }
        CP_COMMIT();
    };

    const int a_row = lane & 15;
    const int a_kb  = (lane >> 4) * 16;
    const int b_nrl = ((lane >> 4) << 3) + (lane & 7);
    const int b_kb  = ((lane >> 3) & 1) * 16;

    stage(0, 0);

    for (int c = 0; c < 32; c++) {
        const int buf = c & 1;
        CP_WAIT0();
        __syncthreads();
        if (c + 1 < 32) stage(c + 1, buf ^ 1);

        const unsigned base = sb + buf * BUFB;
#pragma unroll
        for (int ks = 0; ks < 2; ks++) {
            unsigned ah[4][4], al[4][4], bh[4][2], bl[4][2];
#pragma unroll
            for (int mi = 0; mi < 4; mi++) {
                unsigned ad = base + AHI_ +
                    (unsigned)((wm0 + mi * 16 + a_row) * ROWB + ks * 32 + a_kb);
                ldmx4(ah[mi], ad);
                ldmx4(al[mi], ad + (ALO_ - AHI_));
            }
#pragma unroll
            for (int p = 0; p < 2; p++) {
                unsigned bd = base + BHI_ +
                    (unsigned)((wn0 + p * 16 + b_nrl) * ROWB + ks * 32 + b_kb);
                unsigned r[4];
                ldmx4(r, bd);
                bh[2*p][0] = r[0]; bh[2*p][1] = r[1];
                bh[2*p+1][0] = r[2]; bh[2*p+1][1] = r[3];
                ldmx4(r, bd + (BLO_ - BHI_));
                bl[2*p][0] = r[0]; bl[2*p][1] = r[1];
                bl[2*p+1][0] = r[2]; bl[2*p+1][1] = r[3];
            }
#pragma unroll
            for (int mi = 0; mi < 4; mi++)
#pragma unroll
                for (int ni = 0; ni < 4; ni++) {
                    mma16816(acc[mi][ni], ah[mi], bh[ni][0], bh[ni][1]);
                    mma16816(acc[mi][ni], al[mi], bh[ni][0], bh[ni][1]);
                    mma16816(acc[mi][ni], ah[mi], bl[ni][0], bl[ni][1]);
                }
        }
    }

    const float alpha = lam[lidx];
    const int r  = lane >> 2;
    const int cc = (lane & 3) * 2;
#pragma unroll
    for (int mi = 0; mi < 4; mi++)
#pragma unroll
        for (int ni = 0; ni < 4; ni++) {
            const int row = m0 + wm0 + mi * 16 + r;
            const int col = n0 + wn0 + ni * 8 + cc;
            float2 w0; w0.x = alpha * acc[mi][ni][0]; w0.y = alpha * acc[mi][ni][1];
            float2 w1; w1.x = alpha * acc[mi][ni][2]; w1.y = alpha * acc[mi][ni][3];
            *(float2*)(C + (size_t)row * N + col) = w0;
            *(float2*)(C + (size_t)(row + 8) * N + col) = w1;
        }
}

// ------------- postprocess: rmsnorm + rotary + gates + ve; fp16 out --------
__global__ __launch_bounds__(256) void postproc_kernel(
    const float* __restrict__ x, const float* __restrict__ ve,
    const float* __restrict__ ve_gate_w, const float* __restrict__ attn_gate_w,
    const float* __restrict__ cosb, const float* __restrict__ sinb)
{
    const int t    = blockIdx.x;
    const int w    = threadIdx.x >> 5;
    const int lane = threadIdx.x & 31;
    const float* base = g_qkv + (size_t)t * (3 * DIM_);
    const size_t ob = (size_t)t * DIM_ + w * D_;

    const float c0 = cosb[t * 64 + lane],      s0 = sinb[t * 64 + lane];
    const float c1 = cosb[t * 64 + lane + 32], s1 = sinb[t * 64 + lane + 32];

    {
        const float* qb = base + w * D_;
        float a0 = qb[lane], a1 = qb[lane + 32], a2 = qb[lane + 64], a3 = qb[lane + 96];
        float ss = a0*a0 + a1*a1 + a2*a2 + a3*a3;
#pragma unroll
        for (int off = 16; off; off >>= 1) ss += __shfl_xor_sync(0xffffffffu, ss, off);
        float r = rsqrtf(ss * (1.0f / 128.0f) + 1e-6f);
        a0 *= r; a1 *= r; a2 *= r; a3 *= r;
        g_q16[ob + lane]      = __float2half_rn( a0 * c0 + a2 * s0);
        g_q16[ob + lane + 32] = __float2half_rn( a1 * c1 + a3 * s1);
        g_q16[ob + lane + 64] = __float2half_rn(-a0 * s0 + a2 * c0);
        g_q16[ob + lane + 96] = __float2half_rn(-a1 * s1 + a3 * c1);
    }
    {
        const float* kb = base + DIM_ + w * D_;
        float a0 = kb[lane], a1 = kb[lane + 32], a2 = kb[lane + 64], a3 = kb[lane + 96];
        float ss = a0*a0 + a1*a1 + a2*a2 + a3*a3;
#pragma unroll
        for (int off = 16; off; off >>= 1) ss += __shfl_xor_sync(0xffffffffu, ss, off);
        float r = rsqrtf(ss * (1.0f / 128.0f) + 1e-6f);
        a0 *= r; a1 *= r; a2 *= r; a3 *= r;
        g_k16[ob + lane]      = __float2half_rn( a0 * c0 + a2 * s0);
        g_k16[ob + lane + 32] = __float2half_rn( a1 * c1 + a3 * s1);
        g_k16[ob + lane + 64] = __float2half_rn(-a0 * s0 + a2 * c0);
        g_k16[ob + lane + 96] = __float2half_rn(-a1 * s1 + a3 * c1);
    }
    float xv = (lane < 16) ? x[(size_t)t * DIM_ + lane] : 0.f;
    float dv = (lane < 16) ? xv * ve_gate_w[w * 16 + lane]   : 0.f;
    float da = (lane < 16) ? xv * attn_gate_w[w * 16 + lane] : 0.f;
#pragma unroll
    for (int off = 16; off; off >>= 1) {
        dv += __shfl_xor_sync(0xffffffffu, dv, off);
        da += __shfl_xor_sync(0xffffffffu, da, off);
    }
    const float veg = 2.0f / (1.0f + __expf(-dv));
    if (lane == 0) g_gate[t * H_ + w] = 1.0f / (1.0f + __expf(-da));
    {
        const float* vb  = base + 2 * DIM_ + w * D_;
        const float* vp2 = ve + ob;
        g_v16[ob + lane]      = __float2half_rn(vb[lane]      + veg * vp2[lane]);
        g_v16[ob + lane + 32] = __float2half_rn(vb[lane + 32] + veg * vp2[lane + 32]);
        g_v16[ob + lane + 64] = __float2half_rn(vb[lane + 64] + veg * vp2[lane + 64]);
        g_v16[ob + lane + 96] = __float2half_rn(vb[lane + 96] + veg * vp2[lane + 96]);
    }
}

// ============================================================================
// flash attention: fully single-fp16 operands, 3 CTAs/SM, heavy-first.
// ============================================================================
#define KSTR2 136
#define QH_ 0
#define KH_ 8704
#define VH_ 17408
#define KSEG_B 52224
#define ATTN2_SMEM (52224 + 256)

__global__ __launch_bounds__(128, 3) void attn_mma(
    const int* __restrict__ seg, const int* __restrict__ bm_ptr)
{
    extern __shared__ __align__(128) __half sm2[];
    int* kseg = (int*)((char*)sm2 + KSEG_B);
    const unsigned sb = (unsigned)__cvta_generic_to_shared(sm2);
    const int h   = blockIdx.y;
    const int m0  = ((int)gridDim.x - 1 - (int)blockIdx.x) * 64;  // heavy first
    const int tid = threadIdx.x;
    const int wid = tid >> 5, lane = tid & 31;
    const int bm  = bm_ptr[0];
    const int wr  = wid * 16;

    // stage Q tile via cp.async (64 rows x 128 cols = 1024 uint4 slots)
#pragma unroll
    for (int i = 0; i < 8; i++) {
        int f = tid + i * 128;
        int r = f >> 4, u = f & 15;
        size_t ga = (size_t)(m0 + r) * DIM_ + h * D_ + u * 8;
        cpa16(sb + (unsigned)(QH_ + r * KSTR2 + u * 8) * 2, g_q16 + ga);
    }
    CP_COMMIT();

    const int r_ = lane >> 2, c_ = lane & 3;
    const int tq0 = m0 + wr + r_, tq1 = tq0 + 8;
    const int sq0 = seg[tq0], sq1 = seg[tq1];

    float mi0 = -1e30f, mi1 = -1e30f, li0 = 0.f, li1 = 0.f;
    float o[16][4];
#pragma unroll
    for (int t = 0; t < 16; t++)
#pragma unroll
        for (int e = 0; e < 4; e++) o[t][e] = 0.f;

    const unsigned a_addr = sb + (unsigned)(QH_ + (wr + (lane & 15)) * KSTR2 + (lane >> 4) * 8) * 2;
    const int g  = lane >> 3, gl = lane & 7;
    const unsigned kb_addr = sb + (unsigned)(KH_ + ((g >> 1) * 8 + gl) * KSTR2 + (g & 1) * 8) * 2;
    const unsigned vb_addr = sb + (unsigned)(VH_ + ((g & 1) * 8 + gl) * KSTR2 + (g >> 1) * 8) * 2;

    const int qs0 = seg[m0], qs1 = seg[m0 + 63];
    int kb_lo = m0 - bm; if (kb_lo < 0) kb_lo = 0; kb_lo >>= 6;
    const int kb_hi = m0 >> 6;

    for (int kb = kb_lo; kb <= kb_hi; kb++) {
        const int s0 = kb * 64;
        if (seg[s0 + 63] < qs0 || seg[s0] > qs1) continue;

        __syncthreads();   // prior readers done before restage
#pragma unroll
        for (int i = 0; i < 8; i++) {
            int f = tid + i * 128;
            int r = f >> 4, u = f & 15;
            int t = s0 + r;
            int ts = ((u >> 2) & 1) ? (t > 0 ? t - 1 : 0) : t;
            size_t gk = (size_t)ts * DIM_ + h * D_ + u * 8;
            size_t gv = (size_t)t  * DIM_ + h * D_ + u * 8;
            cpa16(sb + (unsigned)(KH_ + r * KSTR2 + u * 8) * 2, g_k16 + gk);
            cpa16(sb + (unsigned)(VH_ + r * KSTR2 + u * 8) * 2, g_v16 + gv);
        }
        CP_COMMIT();
        if (tid < 64) kseg[tid] = seg[s0 + tid];
        CP_WAIT0();
        __syncthreads();

        // ---- S = Q K^T (single fp16) ----
        float s[8][4];
#pragma unroll
        for (int j = 0; j < 8; j++)
#pragma unroll
            for (int e = 0; e < 4; e++) s[j][e] = 0.f;

#pragma unroll
        for (int kk = 0; kk < 8; kk++) {
            unsigned ah[4];
            ldmx4(ah, a_addr + kk * 32);
#pragma unroll
            for (int jp = 0; jp < 4; jp++) {
                unsigned bh[4];
                ldmx4(bh, kb_addr + (unsigned)(jp * 16 * KSTR2) * 2 + kk * 32);
                mma16816h(s[2*jp],   ah, bh[0], bh[1]);
                mma16816h(s[2*jp+1], ah, bh[2], bh[3]);
            }
        }

        // ---- mask + online softmax ----
        float mx0 = -1e30f, mx1 = -1e30f;
#pragma unroll
        for (int j = 0; j < 8; j++) {
            const int nb = 8 * j + 2 * c_;
            const int tk0 = s0 + nb, tk1 = tk0 + 1;
            const int ka = kseg[nb], kb2 = kseg[nb + 1];
            bool v00 = (tk0 <= tq0) && (tk0 >= tq0 - bm) && (ka  == sq0);
            bool v01 = (tk1 <= tq0) && (tk1 >= tq0 - bm) && (kb2 == sq0);
            bool v10 = (tk0 <= tq1) && (tk0 >= tq1 - bm) && (ka  == sq1);
            bool v11 = (tk1 <= tq1) && (tk1 >= tq1 - bm) && (kb2 == sq1);
            s[j][0] = v00 ? s[j][0] * 0.1f : -1e30f;
            s[j][1] = v01 ? s[j][1] * 0.1f : -1e30f;
            s[j][2] = v10 ? s[j][2] * 0.1f : -1e30f;
            s[j][3] = v11 ? s[j][3] * 0.1f : -1e30f;
            mx0 = fmaxf(mx0, fmaxf(s[j][0], s[j][1]));
            mx1 = fmaxf(mx1, fmaxf(s[j][2], s[j][3]));
        }
        mx0 = fmaxf(mx0, __shfl_xor_sync(0xffffffffu, mx0, 1));
        mx0 = fmaxf(mx0, __shfl_xor_sync(0xffffffffu, mx0, 2));
        mx1 = fmaxf(mx1, __shfl_xor_sync(0xffffffffu, mx1, 1));
        mx1 = fmaxf(mx1, __shfl_xor_sync(0xffffffffu, mx1, 2));

        const float nm0 = fmaxf(mi0, mx0), nm1 = fmaxf(mi1, mx1);
        const float al0 = __expf(mi0 - nm0), al1 = __expf(mi1 - nm1);
        mi0 = nm0; mi1 = nm1;
        float rs0 = 0.f, rs1 = 0.f;
#pragma unroll
        for (int j = 0; j < 8; j++) {
            s[j][0] = __expf(s[j][0] - nm0);
            s[j][1] = __expf(s[j][1] - nm0);
            s[j][2] = __expf(s[j][2] - nm1);
            s[j][3] = __expf(s[j][3] - nm1);
            rs0 += s[j][0] + s[j][1];
            rs1 += s[j][2] + s[j][3];
        }
        rs0 += __shfl_xor_sync(0xffffffffu, rs0, 1);
        rs0 += __shfl_xor_sync(0xffffffffu, rs0, 2);
        rs1 += __shfl_xor_sync(0xffffffffu, rs1, 1);
        rs1 += __shfl_xor_sync(0xffffffffu, rs1, 2);
        li0 = li0 * al0 + rs0;
        li1 = li1 * al1 + rs1;
#pragma unroll
        for (int t = 0; t < 16; t++) {
            o[t][0] *= al0; o[t][1] *= al0;
            o[t][2] *= al1; o[t][3] *= al1;
        }

        // ---- O += P V (single fp16) ----
#pragma unroll
        for (int ss = 0; ss < 4; ss++) {
            unsigned pha[4];
            pha[0] = pack2h(s[2*ss][0],   s[2*ss][1]);
            pha[1] = pack2h(s[2*ss][2],   s[2*ss][3]);
            pha[2] = pack2h(s[2*ss+1][0], s[2*ss+1][1]);
            pha[3] = pack2h(s[2*ss+1][2], s[2*ss+1][3]);
#pragma unroll
            for (int dp = 0; dp < 8; dp++) {
                unsigned bh[4];
                ldmx4t(bh, vb_addr + (unsigned)(ss * 16 * KSTR2) * 2 + dp * 32);
                mma16816h(o[2*dp],   pha, bh[0], bh[1]);
                mma16816h(o[2*dp+1], pha, bh[2], bh[3]);
            }
        }
    }

    // ---- epilogue: normalize, gate, store y as bf16 hi/lo planes ----
    const float gg0 = g_gate[tq0 * H_ + h], gg1 = g_gate[tq1 * H_ + h];
    const float i0 = gg0 / li0, i1 = gg1 / li1;
#pragma unroll
    for (int t = 0; t < 16; t++) {
        size_t idx0 = (size_t)tq0 * DIM_ + h * D_ + 8 * t + 2 * c_;
        size_t idx1 = (size_t)tq1 * DIM_ + h * D_ + 8 * t + 2 * c_;
        unsigned lw;
        unsigned hw = packsplit(o[t][0] * i0, o[t][1] * i0, lw);
        *(unsigned*)(g_yh + idx0) = hw;
        *(unsigned*)(g_yl + idx0) = lw;
        hw = packsplit(o[t][2] * i1, o[t][3] * i1, lw);
        *(unsigned*)(g_yh + idx1) = hw;
        *(unsigned*)(g_yl + idx1) = lw;
    }
}

// ---------------------------------------------------------------------------
extern "C" void kernel_launch(void* const* d_in, const int* in_sizes, int n_in,
                              void* d_out, int out_size)
{
    const float* x    = (const float*)d_in[0];
    const float* qkvo = (const float*)d_in[1];
    const float* lam  = (const float*)d_in[2];
    const float* ve   = (const float*)d_in[3];
    const float* agw  = (const float*)d_in[4];
    const float* vgw  = (const float*)d_in[5];
    const float* cosb = (const float*)d_in[6];
    const float* sinb = (const float*)d_in[7];
    const int*   seg  = (const int*)d_in[8];
    const int*   bmp  = (const int*)d_in[9];
    float*       out  = (float*)d_out;

    float *p_qkv;
    __nv_bfloat16 *p_xh, *p_xl, *p_wh, *p_wl, *p_yh, *p_yl;
    cudaGetSymbolAddress((void**)&p_qkv, g_qkv);
    cudaGetSymbolAddress((void**)&p_xh, g_xh);
    cudaGetSymbolAddress((void**)&p_xl, g_xl);
    cudaGetSymbolAddress((void**)&p_wh, g_wh);
    cudaGetSymbolAddress((void**)&p_wl, g_wl);
    cudaGetSymbolAddress((void**)&p_yh, g_yh);
    cudaGetSymbolAddress((void**)&p_yl, g_yl);

    cudaFuncSetAttribute(gemm_bf16s,
                         cudaFuncAttributeMaxDynamicSharedMemorySize, GEMM_SMEM);
    cudaFuncSetAttribute(attn_mma,
                         cudaFuncAttributeMaxDynamicSharedMemorySize, ATTN2_SMEM);

    // 0. one-time splits
    convert_split<<<T_ * DIM_ / 1024, 256>>>((const float4*)x,
                                             (uint2*)p_xh, (uint2*)p_xl,
                                             T_ * DIM_ / 4);
    convert_split<<<4 * DIM_ * DIM_ / 1024, 256>>>((const float4*)qkvo,
                                                   (uint2*)p_wh, (uint2*)p_wl,
                                                   4 * DIM_ * DIM_ / 4);

    // 1. qkv = lam0 * x @ Wqkv^T   [3072 x 3072]
    gemm_bf16s<<<dim3(24, 24), 256, GEMM_SMEM>>>(p_xh, p_xl, p_wh, p_wl,
                                                 p_qkv, 3072, lam, 0);

    // 2. rmsnorm + rotary + gates + ve add -> fp16 planes
    postproc_kernel<<<T_, 256>>>(x, ve, vgw, agw, cosb, sinb);

    // 3. attention (single fp16; 3 CTAs/SM; k-shift fused; heavy-first)
    attn_mma<<<dim3(T_ / 64, H_), 128, ATTN2_SMEM>>>(seg, bmp);

    // 4. out = lam1 * y @ Wo^T   [3072 x 1024]
    gemm_bf16s<<<dim3(8, 24), 256, GEMM_SMEM>>>(
        p_yh, p_yl, p_wh + (size_t)3 * DIM_ * DIM_, p_wl + (size_t)3 * DIM_ * DIM_,
        out, 1024, lam, 1);
}

// round 16
// speedup vs baseline: 2.2066x; 1.2609x over previous
#include <cuda_runtime.h>
#include <cuda_bf16.h>
#include <cuda_fp16.h>
#include <math.h>
#include <stdint.h>

#define T_   3072
#define DIM_ 1024
#define H_   8
#define D_   128

// ---------------- scratch (device globals: no allocation allowed) ----------
__device__ float g_qkv[(size_t)T_ * 3 * DIM_];
__device__ float g_gate[T_ * H_];
__device__ __half g_x16[(size_t)T_ * DIM_];
__device__ __half g_w16h[(size_t)4 * DIM_ * DIM_], g_w16l[(size_t)4 * DIM_ * DIM_];
__device__ __half g_q16[(size_t)T_ * DIM_];
__device__ __half g_k16[(size_t)T_ * DIM_];
__device__ __half g_v16[(size_t)T_ * DIM_];
__device__ __half g_y16[(size_t)T_ * DIM_];

// ---------------- helpers ---------------------------------------------------
__device__ __forceinline__ void cpa16(unsigned dst, const void* src) {
    asm volatile("cp.async.cg.shared.global [%0],[%1],16;" :: "r"(dst), "l"(src));
}
#define CP_COMMIT() asm volatile("cp.async.commit_group;" ::: "memory")
#define CP_WAIT0()  asm volatile("cp.async.wait_group 0;" ::: "memory")

__device__ __forceinline__ void ldmx4(unsigned r[4], unsigned addr) {
    asm volatile("ldmatrix.sync.aligned.m8n8.x4.shared.b16 {%0,%1,%2,%3},[%4];"
                 : "=r"(r[0]), "=r"(r[1]), "=r"(r[2]), "=r"(r[3]) : "r"(addr));
}
__device__ __forceinline__ void ldmx4t(unsigned r[4], unsigned addr) {
    asm volatile("ldmatrix.sync.aligned.m8n8.x4.trans.shared.b16 {%0,%1,%2,%3},[%4];"
                 : "=r"(r[0]), "=r"(r[1]), "=r"(r[2]), "=r"(r[3]) : "r"(addr));
}
__device__ __forceinline__ void mma16816h(float c[4], const unsigned a[4],
                                          const unsigned b0, const unsigned b1) {
    asm volatile("mma.sync.aligned.m16n8k16.row.col.f32.f16.f16.f32 "
                 "{%0,%1,%2,%3},{%4,%5,%6,%7},{%8,%9},{%0,%1,%2,%3};"
                 : "+f"(c[0]), "+f"(c[1]), "+f"(c[2]), "+f"(c[3])
                 : "r"(a[0]), "r"(a[1]), "r"(a[2]), "r"(a[3]), "r"(b0), "r"(b1));
}
__device__ __forceinline__ unsigned pack2h(float p0, float p1) {
    __half h0 = __float2half_rn(p0), h1 = __float2half_rn(p1);
    return (unsigned)__half_as_ushort(h0) | ((unsigned)__half_as_ushort(h1) << 16);
}

// ---------------- one-time conversions --------------------------------------
__global__ __launch_bounds__(256) void convert_h(
    const float4* __restrict__ src, uint2* __restrict__ d, int n4)
{
    int i = blockIdx.x * 256 + threadIdx.x;
    if (i < n4) {
        float4 v = src[i];
        uint2 o;
        o.x = pack2h(v.x, v.y);
        o.y = pack2h(v.z, v.w);
        d[i] = o;
    }
}
__global__ __launch_bounds__(256) void convert_split_h(
    const float4* __restrict__ src, uint2* __restrict__ dh,
    uint2* __restrict__ dl, int n4)
{
    int i = blockIdx.x * 256 + threadIdx.x;
    if (i < n4) {
        float4 v = src[i];
        __half hx = __float2half_rn(v.x), hy = __float2half_rn(v.y);
        __half hz = __float2half_rn(v.z), hw = __float2half_rn(v.w);
        uint2 oh, ol;
        oh.x = (unsigned)__half_as_ushort(hx) | ((unsigned)__half_as_ushort(hy) << 16);
        oh.y = (unsigned)__half_as_ushort(hz) | ((unsigned)__half_as_ushort(hw) << 16);
        ol.x = pack2h(v.x - __half2float(hx), v.y - __half2float(hy));
        ol.y = pack2h(v.z - __half2float(hz), v.w - __half2float(hw));
        dh[i] = oh;
        dl[i] = ol;
    }
}

// ============================================================================
// fp16 asymmetric-split GEMM: C = lam * A(fp16) @ (Bh+Bl)(fp16)^T, K=1024.
// Tile 128x128, k-chunk 32, cp.async staging, 2 CTAs/SM.
// ============================================================================
#define ROWB  80
#define A_    0
#define BH_   10240
#define BL_   20480
#define BUFB  30720
#define GEMM_SMEM (2 * BUFB)

__global__ __launch_bounds__(256, 2) void gemm_f16s(
    const __half* __restrict__ A, const __half* __restrict__ Bh,
    const __half* __restrict__ Bl,
    float* __restrict__ C, int N, const float* __restrict__ lam, int lidx)
{
    extern __shared__ __align__(128) char smem[];
    const unsigned sb = (unsigned)__cvta_generic_to_shared(smem);
    const int tid  = threadIdx.x;
    const int wid  = tid >> 5;
    const int lane = tid & 31;
    const int m0 = blockIdx.y * 128;
    const int n0 = blockIdx.x * 128;
    const int wm0 = (wid & 1) * 64;
    const int wn0 = (wid >> 1) * 32;

    float acc[4][4][4];
#pragma unroll
    for (int mi = 0; mi < 4; mi++)
#pragma unroll
        for (int ni = 0; ni < 4; ni++)
#pragma unroll
            for (int e = 0; e < 4; e++) acc[mi][ni][e] = 0.f;

    auto stage = [&](int c, int buf) {
        const int kc = c * 32;
        const unsigned bb = sb + buf * BUFB;
#pragma unroll
        for (int i = 0; i < 2; i++) {
            int f = tid + i * 256;
            int row = f >> 2, q = f & 3;
            size_t ga = (size_t)(m0 + row) * 1024 + kc + q * 8;
            size_t gb = (size_t)(n0 + row) * 1024 + kc + q * 8;
            unsigned so = (unsigned)(row * ROWB + q * 16);
            cpa16(bb + A_ + so,  A  + ga);
            cpa16(bb + BH_ + so, Bh + gb);
            cpa16(bb + BL_ + so, Bl + gb);
        }
        CP_COMMIT();
    };

    const int a_row = lane & 15;
    const int a_kb  = (lane >> 4) * 16;
    const int b_nrl = ((lane >> 4) << 3) + (lane & 7);
    const int b_kb  = ((lane >> 3) & 1) * 16;

    stage(0, 0);

    for (int c = 0; c < 32; c++) {
        const int buf = c & 1;
        CP_WAIT0();
        __syncthreads();
        if (c + 1 < 32) stage(c + 1, buf ^ 1);

        const unsigned base = sb + buf * BUFB;
#pragma unroll
        for (int ks = 0; ks < 2; ks++) {
            unsigned ah[4][4], bh[4][2], bl[4][2];
#pragma unroll
            for (int mi = 0; mi < 4; mi++) {
                unsigned ad = base + A_ +
                    (unsigned)((wm0 + mi * 16 + a_row) * ROWB + ks * 32 + a_kb);
                ldmx4(ah[mi], ad);
            }
#pragma unroll
            for (int p = 0; p < 2; p++) {
                unsigned bd = base + BH_ +
                    (unsigned)((wn0 + p * 16 + b_nrl) * ROWB + ks * 32 + b_kb);
                unsigned r[4];
                ldmx4(r, bd);
                bh[2*p][0] = r[0]; bh[2*p][1] = r[1];
                bh[2*p+1][0] = r[2]; bh[2*p+1][1] = r[3];
                ldmx4(r, bd + (BL_ - BH_));
                bl[2*p][0] = r[0]; bl[2*p][1] = r[1];
                bl[2*p+1][0] = r[2]; bl[2*p+1][1] = r[3];
            }
#pragma unroll
            for (int mi = 0; mi < 4; mi++)
#pragma unroll
                for (int ni = 0; ni < 4; ni++) {
                    mma16816h(acc[mi][ni], ah[mi], bh[ni][0], bh[ni][1]);
                    mma16816h(acc[mi][ni], ah[mi], bl[ni][0], bl[ni][1]);
                }
        }
    }

    const float alpha = lam[lidx];
    const int r  = lane >> 2;
    const int cc = (lane & 3) * 2;
#pragma unroll
    for (int mi = 0; mi < 4; mi++)
#pragma unroll
        for (int ni = 0; ni < 4; ni++) {
            const int row = m0 + wm0 + mi * 16 + r;
            const int col = n0 + wn0 + ni * 8 + cc;
            float2 w0; w0.x = alpha * acc[mi][ni][0]; w0.y = alpha * acc[mi][ni][1];
            float2 w1; w1.x = alpha * acc[mi][ni][2]; w1.y = alpha * acc[mi][ni][3];
            *(float2*)(C + (size_t)row * N + col) = w0;
            *(float2*)(C + (size_t)(row + 8) * N + col) = w1;
        }
}

// ------------- postprocess: rmsnorm + rotary + gates + ve; fp16 out --------
__global__ __launch_bounds__(256) void postproc_kernel(
    const float* __restrict__ x, const float* __restrict__ ve,
    const float* __restrict__ ve_gate_w, const float* __restrict__ attn_gate_w,
    const float* __restrict__ cosb, const float* __restrict__ sinb)
{
    const int t    = blockIdx.x;
    const int w    = threadIdx.x >> 5;
    const int lane = threadIdx.x & 31;
    const float* base = g_qkv + (size_t)t * (3 * DIM_);
    const size_t ob = (size_t)t * DIM_ + w * D_;

    const float c0 = cosb[t * 64 + lane],      s0 = sinb[t * 64 + lane];
    const float c1 = cosb[t * 64 + lane + 32], s1 = sinb[t * 64 + lane + 32];

    {
        const float* qb = base + w * D_;
        float a0 = qb[lane], a1 = qb[lane + 32], a2 = qb[lane + 64], a3 = qb[lane + 96];
        float ss = a0*a0 + a1*a1 + a2*a2 + a3*a3;
#pragma unroll
        for (int off = 16; off; off >>= 1) ss += __shfl_xor_sync(0xffffffffu, ss, off);
        float r = rsqrtf(ss * (1.0f / 128.0f) + 1e-6f);
        a0 *= r; a1 *= r; a2 *= r; a3 *= r;
        g_q16[ob + lane]      = __float2half_rn( a0 * c0 + a2 * s0);
        g_q16[ob + lane + 32] = __float2half_rn( a1 * c1 + a3 * s1);
        g_q16[ob + lane + 64] = __float2half_rn(-a0 * s0 + a2 * c0);
        g_q16[ob + lane + 96] = __float2half_rn(-a1 * s1 + a3 * c1);
    }
    {
        const float* kb = base + DIM_ + w * D_;
        float a0 = kb[lane], a1 = kb[lane + 32], a2 = kb[lane + 64], a3 = kb[lane + 96];
        float ss = a0*a0 + a1*a1 + a2*a2 + a3*a3;
#pragma unroll
        for (int off = 16; off; off >>= 1) ss += __shfl_xor_sync(0xffffffffu, ss, off);
        float r = rsqrtf(ss * (1.0f / 128.0f) + 1e-6f);
        a0 *= r; a1 *= r; a2 *= r; a3 *= r;
        g_k16[ob + lane]      = __float2half_rn( a0 * c0 + a2 * s0);
        g_k16[ob + lane + 32] = __float2half_rn( a1 * c1 + a3 * s1);
        g_k16[ob + lane + 64] = __float2half_rn(-a0 * s0 + a2 * c0);
        g_k16[ob + lane + 96] = __float2half_rn(-a1 * s1 + a3 * c1);
    }
    float xv = (lane < 16) ? x[(size_t)t * DIM_ + lane] : 0.f;
    float dv = (lane < 16) ? xv * ve_gate_w[w * 16 + lane]   : 0.f;
    float da = (lane < 16) ? xv * attn_gate_w[w * 16 + lane] : 0.f;
#pragma unroll
    for (int off = 16; off; off >>= 1) {
        dv += __shfl_xor_sync(0xffffffffu, dv, off);
        da += __shfl_xor_sync(0xffffffffu, da, off);
    }
    const float veg = 2.0f / (1.0f + __expf(-dv));
    if (lane == 0) g_gate[t * H_ + w] = 1.0f / (1.0f + __expf(-da));
    {
        const float* vb  = base + 2 * DIM_ + w * D_;
        const float* vp2 = ve + ob;
        g_v16[ob + lane]      = __float2half_rn(vb[lane]      + veg * vp2[lane]);
        g_v16[ob + lane + 32] = __float2half_rn(vb[lane + 32] + veg * vp2[lane + 32]);
        g_v16[ob + lane + 64] = __float2half_rn(vb[lane + 64] + veg * vp2[lane + 64]);
        g_v16[ob + lane + 96] = __float2half_rn(vb[lane + 96] + veg * vp2[lane + 96]);
    }
}

// ============================================================================
// flash attention: fully single-fp16 operands, 3 CTAs/SM, heavy-first.
// (R15 WIN, unchanged except y stored as single fp16)
// ============================================================================
#define KSTR2 136
#define QH_ 0
#define KH_ 8704
#define VH_ 17408
#define KSEG_B 52224
#define ATTN2_SMEM (52224 + 256)

__global__ __launch_bounds__(128, 3) void attn_mma(
    const int* __restrict__ seg, const int* __restrict__ bm_ptr)
{
    extern __shared__ __align__(128) __half sm2[];
    int* kseg = (int*)((char*)sm2 + KSEG_B);
    const unsigned sb = (unsigned)__cvta_generic_to_shared(sm2);
    const int h   = blockIdx.y;
    const int m0  = ((int)gridDim.x - 1 - (int)blockIdx.x) * 64;  // heavy first
    const int tid = threadIdx.x;
    const int wid = tid >> 5, lane = tid & 31;
    const int bm  = bm_ptr[0];
    const int wr  = wid * 16;

    // stage Q tile via cp.async (64 rows x 128 cols = 1024 uint4 slots)
#pragma unroll
    for (int i = 0; i < 8; i++) {
        int f = tid + i * 128;
        int r = f >> 4, u = f & 15;
        size_t ga = (size_t)(m0 + r) * DIM_ + h * D_ + u * 8;
        cpa16(sb + (unsigned)(QH_ + r * KSTR2 + u * 8) * 2, g_q16 + ga);
    }
    CP_COMMIT();

    const int r_ = lane >> 2, c_ = lane & 3;
    const int tq0 = m0 + wr + r_, tq1 = tq0 + 8;
    const int sq0 = seg[tq0], sq1 = seg[tq1];

    float mi0 = -1e30f, mi1 = -1e30f, li0 = 0.f, li1 = 0.f;
    float o[16][4];
#pragma unroll
    for (int t = 0; t < 16; t++)
#pragma unroll
        for (int e = 0; e < 4; e++) o[t][e] = 0.f;

    const unsigned a_addr = sb + (unsigned)(QH_ + (wr + (lane & 15)) * KSTR2 + (lane >> 4) * 8) * 2;
    const int g  = lane >> 3, gl = lane & 7;
    const unsigned kb_addr = sb + (unsigned)(KH_ + ((g >> 1) * 8 + gl) * KSTR2 + (g & 1) * 8) * 2;
    const unsigned vb_addr = sb + (unsigned)(VH_ + ((g & 1) * 8 + gl) * KSTR2 + (g >> 1) * 8) * 2;

    const int qs0 = seg[m0], qs1 = seg[m0 + 63];
    int kb_lo = m0 - bm; if (kb_lo < 0) kb_lo = 0; kb_lo >>= 6;
    const int kb_hi = m0 >> 6;

    for (int kb = kb_lo; kb <= kb_hi; kb++) {
        const int s0 = kb * 64;
        if (seg[s0 + 63] < qs0 || seg[s0] > qs1) continue;

        __syncthreads();   // prior readers done before restage
#pragma unroll
        for (int i = 0; i < 8; i++) {
            int f = tid + i * 128;
            int r = f >> 4, u = f & 15;
            int t = s0 + r;
            int ts = ((u >> 2) & 1) ? (t > 0 ? t - 1 : 0) : t;
            size_t gk = (size_t)ts * DIM_ + h * D_ + u * 8;
            size_t gv = (size_t)t  * DIM_ + h * D_ + u * 8;
            cpa16(sb + (unsigned)(KH_ + r * KSTR2 + u * 8) * 2, g_k16 + gk);
            cpa16(sb + (unsigned)(VH_ + r * KSTR2 + u * 8) * 2, g_v16 + gv);
        }
        CP_COMMIT();
        if (tid < 64) kseg[tid] = seg[s0 + tid];
        CP_WAIT0();
        __syncthreads();

        // ---- S = Q K^T (single fp16) ----
        float s[8][4];
#pragma unroll
        for (int j = 0; j < 8; j++)
#pragma unroll
            for (int e = 0; e < 4; e++) s[j][e] = 0.f;

#pragma unroll
        for (int kk = 0; kk < 8; kk++) {
            unsigned ah[4];
            ldmx4(ah, a_addr + kk * 32);
#pragma unroll
            for (int jp = 0; jp < 4; jp++) {
                unsigned bh[4];
                ldmx4(bh, kb_addr + (unsigned)(jp * 16 * KSTR2) * 2 + kk * 32);
                mma16816h(s[2*jp],   ah, bh[0], bh[1]);
                mma16816h(s[2*jp+1], ah, bh[2], bh[3]);
            }
        }

        // ---- mask + online softmax ----
        float mx0 = -1e30f, mx1 = -1e30f;
#pragma unroll
        for (int j = 0; j < 8; j++) {
            const int nb = 8 * j + 2 * c_;
            const int tk0 = s0 + nb, tk1 = tk0 + 1;
            const int ka = kseg[nb], kb2 = kseg[nb + 1];
            bool v00 = (tk0 <= tq0) && (tk0 >= tq0 - bm) && (ka  == sq0);
            bool v01 = (tk1 <= tq0) && (tk1 >= tq0 - bm) && (kb2 == sq0);
            bool v10 = (tk0 <= tq1) && (tk0 >= tq1 - bm) && (ka  == sq1);
            bool v11 = (tk1 <= tq1) && (tk1 >= tq1 - bm) && (kb2 == sq1);
            s[j][0] = v00 ? s[j][0] * 0.1f : -1e30f;
            s[j][1] = v01 ? s[j][1] * 0.1f : -1e30f;
            s[j][2] = v10 ? s[j][2] * 0.1f : -1e30f;
            s[j][3] = v11 ? s[j][3] * 0.1f : -1e30f;
            mx0 = fmaxf(mx0, fmaxf(s[j][0], s[j][1]));
            mx1 = fmaxf(mx1, fmaxf(s[j][2], s[j][3]));
        }
        mx0 = fmaxf(mx0, __shfl_xor_sync(0xffffffffu, mx0, 1));
        mx0 = fmaxf(mx0, __shfl_xor_sync(0xffffffffu, mx0, 2));
        mx1 = fmaxf(mx1, __shfl_xor_sync(0xffffffffu, mx1, 1));
        mx1 = fmaxf(mx1, __shfl_xor_sync(0xffffffffu, mx1, 2));

        const float nm0 = fmaxf(mi0, mx0), nm1 = fmaxf(mi1, mx1);
        const float al0 = __expf(mi0 - nm0), al1 = __expf(mi1 - nm1);
        mi0 = nm0; mi1 = nm1;
        float rs0 = 0.f, rs1 = 0.f;
#pragma unroll
        for (int j = 0; j < 8; j++) {
            s[j][0] = __expf(s[j][0] - nm0);
            s[j][1] = __expf(s[j][1] - nm0);
            s[j][2] = __expf(s[j][2] - nm1);
            s[j][3] = __expf(s[j][3] - nm1);
            rs0 += s[j][0] + s[j][1];
            rs1 += s[j][2] + s[j][3];
        }
        rs0 += __shfl_xor_sync(0xffffffffu, rs0, 1);
        rs0 += __shfl_xor_sync(0xffffffffu, rs0, 2);
        rs1 += __shfl_xor_sync(0xffffffffu, rs1, 1);
        rs1 += __shfl_xor_sync(0xffffffffu, rs1, 2);
        li0 = li0 * al0 + rs0;
        li1 = li1 * al1 + rs1;
#pragma unroll
        for (int t = 0; t < 16; t++) {
            o[t][0] *= al0; o[t][1] *= al0;
            o[t][2] *= al1; o[t][3] *= al1;
        }

        // ---- O += P V (single fp16) ----
#pragma unroll
        for (int ss = 0; ss < 4; ss++) {
            unsigned pha[4];
            pha[0] = pack2h(s[2*ss][0],   s[2*ss][1]);
            pha[1] = pack2h(s[2*ss][2],   s[2*ss][3]);
            pha[2] = pack2h(s[2*ss+1][0], s[2*ss+1][1]);
            pha[3] = pack2h(s[2*ss+1][2], s[2*ss+1][3]);
#pragma unroll
            for (int dp = 0; dp < 8; dp++) {
                unsigned bh[4];
                ldmx4t(bh, vb_addr + (unsigned)(ss * 16 * KSTR2) * 2 + dp * 32);
                mma16816h(o[2*dp],   pha, bh[0], bh[1]);
                mma16816h(o[2*dp+1], pha, bh[2], bh[3]);
            }
        }
    }

    // ---- epilogue: normalize, gate, store y as single fp16 ----
    const float gg0 = g_gate[tq0 * H_ + h], gg1 = g_gate[tq1 * H_ + h];
    const float i0 = gg0 / li0, i1 = gg1 / li1;
#pragma unroll
    for (int t = 0; t < 16; t++) {
        size_t idx0 = (size_t)tq0 * DIM_ + h * D_ + 8 * t + 2 * c_;
        size_t idx1 = (size_t)tq1 * DIM_ + h * D_ + 8 * t + 2 * c_;
        *(unsigned*)(g_y16 + idx0) = pack2h(o[t][0] * i0, o[t][1] * i0);
        *(unsigned*)(g_y16 + idx1) = pack2h(o[t][2] * i1, o[t][3] * i1);
    }
}

// ---------------------------------------------------------------------------
extern "C" void kernel_launch(void* const* d_in, const int* in_sizes, int n_in,
                              void* d_out, int out_size)
{
    const float* x    = (const float*)d_in[0];
    const float* qkvo = (const float*)d_in[1];
    const float* lam  = (const float*)d_in[2];
    const float* ve   = (const float*)d_in[3];
    const float* agw  = (const float*)d_in[4];
    const float* vgw  = (const float*)d_in[5];
    const float* cosb = (const float*)d_in[6];
    const float* sinb = (const float*)d_in[7];
    const int*   seg  = (const int*)d_in[8];
    const int*   bmp  = (const int*)d_in[9];
    float*       out  = (float*)d_out;

    float *p_qkv;
    __half *p_x16, *p_wh, *p_wl, *p_y16;
    cudaGetSymbolAddress((void**)&p_qkv, g_qkv);
    cudaGetSymbolAddress((void**)&p_x16, g_x16);
    cudaGetSymbolAddress((void**)&p_wh,  g_w16h);
    cudaGetSymbolAddress((void**)&p_wl,  g_w16l);
    cudaGetSymbolAddress((void**)&p_y16, g_y16);

    cudaFuncSetAttribute(gemm_f16s,
                         cudaFuncAttributeMaxDynamicSharedMemorySize, GEMM_SMEM);
    cudaFuncSetAttribute(attn_mma,
                         cudaFuncAttributeMaxDynamicSharedMemorySize, ATTN2_SMEM);

    // 0. one-time conversions
    convert_h<<<T_ * DIM_ / 1024, 256>>>((const float4*)x,
                                         (uint2*)p_x16, T_ * DIM_ / 4);
    convert_split_h<<<4 * DIM_ * DIM_ / 1024, 256>>>(
        (const float4*)qkvo, (uint2*)p_wh, (uint2*)p_wl, 4 * DIM_ * DIM_ / 4);

    // 1. qkv = lam0 * x @ Wqkv^T   [3072 x 3072]  (fp16 asymmetric split)
    gemm_f16s<<<dim3(24, 24), 256, GEMM_SMEM>>>(p_x16, p_wh, p_wl,
                                                p_qkv, 3072, lam, 0);

    // 2. rmsnorm + rotary + gates + ve add -> fp16 planes
    postproc_kernel<<<T_, 256>>>(x, ve, vgw, agw, cosb, sinb);

    // 3. attention (single fp16; 3 CTAs/SM; k-shift fused; heavy-first)
    attn_mma<<<dim3(T_ / 64, H_), 128, ATTN2_SMEM>>>(seg, bmp);

    // 4. out = lam1 * y @ Wo^T   [3072 x 1024]  (fp16 asymmetric split)
    gemm_f16s<<<dim3(8, 24), 256, GEMM_SMEM>>>(
        p_y16, p_wh + (size_t)3 * DIM_ * DIM_, p_wl + (size_t)3 * DIM_ * DIM_,
        out, 1024, lam, 1);
}

// round 17
// speedup vs baseline: 2.2552x; 1.0220x over previous
#include <cuda_runtime.h>
#include <cuda_bf16.h>
#include <cuda_fp16.h>
#include <math.h>
#include <stdint.h>

#define T_   3072
#define DIM_ 1024
#define H_   8
#define D_   128

// ---------------- scratch (device globals: no allocation allowed) ----------
__device__ float g_qkv[(size_t)T_ * 3 * DIM_];
__device__ float g_gate[T_ * H_];
__device__ __half g_x16[(size_t)T_ * DIM_];
__device__ __half g_w16h[(size_t)4 * DIM_ * DIM_], g_w16l[(size_t)4 * DIM_ * DIM_];
__device__ __half g_q16[(size_t)T_ * DIM_];
__device__ __half g_k16[(size_t)T_ * DIM_];
__device__ __half g_v16[(size_t)T_ * DIM_];
__device__ __half g_y16[(size_t)T_ * DIM_];

// ---------------- helpers ---------------------------------------------------
__device__ __forceinline__ void cpa16(unsigned dst, const void* src) {
    asm volatile("cp.async.cg.shared.global [%0],[%1],16;" :: "r"(dst), "l"(src));
}
#define CP_COMMIT() asm volatile("cp.async.commit_group;" ::: "memory")
#define CP_WAIT0()  asm volatile("cp.async.wait_group 0;" ::: "memory")

__device__ __forceinline__ void ldmx4(unsigned r[4], unsigned addr) {
    asm volatile("ldmatrix.sync.aligned.m8n8.x4.shared.b16 {%0,%1,%2,%3},[%4];"
                 : "=r"(r[0]), "=r"(r[1]), "=r"(r[2]), "=r"(r[3]) : "r"(addr));
}
__device__ __forceinline__ void ldmx4t(unsigned r[4], unsigned addr) {
    asm volatile("ldmatrix.sync.aligned.m8n8.x4.trans.shared.b16 {%0,%1,%2,%3},[%4];"
                 : "=r"(r[0]), "=r"(r[1]), "=r"(r[2]), "=r"(r[3]) : "r"(addr));
}
__device__ __forceinline__ void mma16816h(float c[4], const unsigned a[4],
                                          const unsigned b0, const unsigned b1) {
    asm volatile("mma.sync.aligned.m16n8k16.row.col.f32.f16.f16.f32 "
                 "{%0,%1,%2,%3},{%4,%5,%6,%7},{%8,%9},{%0,%1,%2,%3};"
                 : "+f"(c[0]), "+f"(c[1]), "+f"(c[2]), "+f"(c[3])
                 : "r"(a[0]), "r"(a[1]), "r"(a[2]), "r"(a[3]), "r"(b0), "r"(b1));
}
__device__ __forceinline__ unsigned pack2h(float p0, float p1) {
    __half h0 = __float2half_rn(p0), h1 = __float2half_rn(p1);
    return (unsigned)__half_as_ushort(h0) | ((unsigned)__half_as_ushort(h1) << 16);
}

// ---------------- one-time conversions --------------------------------------
__global__ __launch_bounds__(256) void convert_h(
    const float4* __restrict__ src, uint2* __restrict__ d, int n4)
{
    int i = blockIdx.x * 256 + threadIdx.x;
    if (i < n4) {
        float4 v = src[i];
        uint2 o;
        o.x = pack2h(v.x, v.y);
        o.y = pack2h(v.z, v.w);
        d[i] = o;
    }
}
__global__ __launch_bounds__(256) void convert_split_h(
    const float4* __restrict__ src, uint2* __restrict__ dh,
    uint2* __restrict__ dl, int n4)
{
    int i = blockIdx.x * 256 + threadIdx.x;
    if (i < n4) {
        float4 v = src[i];
        __half hx = __float2half_rn(v.x), hy = __float2half_rn(v.y);
        __half hz = __float2half_rn(v.z), hw = __float2half_rn(v.w);
        uint2 oh, ol;
        oh.x = (unsigned)__half_as_ushort(hx) | ((unsigned)__half_as_ushort(hy) << 16);
        oh.y = (unsigned)__half_as_ushort(hz) | ((unsigned)__half_as_ushort(hw) << 16);
        ol.x = pack2h(v.x - __half2float(hx), v.y - __half2float(hy));
        ol.y = pack2h(v.z - __half2float(hz), v.w - __half2float(hw));
        dh[i] = oh;
        dl[i] = ol;
    }
}

// ============================================================================
// fp16 asymmetric-split GEMM (R16 WIN, unchanged)
// ============================================================================
#define ROWB  80
#define A_    0
#define BH_   10240
#define BL_   20480
#define BUFB  30720
#define GEMM_SMEM (2 * BUFB)

__global__ __launch_bounds__(256, 2) void gemm_f16s(
    const __half* __restrict__ A, const __half* __restrict__ Bh,
    const __half* __restrict__ Bl,
    float* __restrict__ C, int N, const float* __restrict__ lam, int lidx)
{
    extern __shared__ __align__(128) char smem[];
    const unsigned sb = (unsigned)__cvta_generic_to_shared(smem);
    const int tid  = threadIdx.x;
    const int wid  = tid >> 5;
    const int lane = tid & 31;
    const int m0 = blockIdx.y * 128;
    const int n0 = blockIdx.x * 128;
    const int wm0 = (wid & 1) * 64;
    const int wn0 = (wid >> 1) * 32;

    float acc[4][4][4];
#pragma unroll
    for (int mi = 0; mi < 4; mi++)
#pragma unroll
        for (int ni = 0; ni < 4; ni++)
#pragma unroll
            for (int e = 0; e < 4; e++) acc[mi][ni][e] = 0.f;

    auto stage = [&](int c, int buf) {
        const int kc = c * 32;
        const unsigned bb = sb + buf * BUFB;
#pragma unroll
        for (int i = 0; i < 2; i++) {
            int f = tid + i * 256;
            int row = f >> 2, q = f & 3;
            size_t ga = (size_t)(m0 + row) * 1024 + kc + q * 8;
            size_t gb = (size_t)(n0 + row) * 1024 + kc + q * 8;
            unsigned so = (unsigned)(row * ROWB + q * 16);
            cpa16(bb + A_ + so,  A  + ga);
            cpa16(bb + BH_ + so, Bh + gb);
            cpa16(bb + BL_ + so, Bl + gb);
        }
        CP_COMMIT();
    };

    const int a_row = lane & 15;
    const int a_kb  = (lane >> 4) * 16;
    const int b_nrl = ((lane >> 4) << 3) + (lane & 7);
    const int b_kb  = ((lane >> 3) & 1) * 16;

    stage(0, 0);

    for (int c = 0; c < 32; c++) {
        const int buf = c & 1;
        CP_WAIT0();
        __syncthreads();
        if (c + 1 < 32) stage(c + 1, buf ^ 1);

        const unsigned base = sb + buf * BUFB;
#pragma unroll
        for (int ks = 0; ks < 2; ks++) {
            unsigned ah[4][4], bh[4][2], bl[4][2];
#pragma unroll
            for (int mi = 0; mi < 4; mi++) {
                unsigned ad = base + A_ +
                    (unsigned)((wm0 + mi * 16 + a_row) * ROWB + ks * 32 + a_kb);
                ldmx4(ah[mi], ad);
            }
#pragma unroll
            for (int p = 0; p < 2; p++) {
                unsigned bd = base + BH_ +
                    (unsigned)((wn0 + p * 16 + b_nrl) * ROWB + ks * 32 + b_kb);
                unsigned r[4];
                ldmx4(r, bd);
                bh[2*p][0] = r[0]; bh[2*p][1] = r[1];
                bh[2*p+1][0] = r[2]; bh[2*p+1][1] = r[3];
                ldmx4(r, bd + (BL_ - BH_));
                bl[2*p][0] = r[0]; bl[2*p][1] = r[1];
                bl[2*p+1][0] = r[2]; bl[2*p+1][1] = r[3];
            }
#pragma unroll
            for (int mi = 0; mi < 4; mi++)
#pragma unroll
                for (int ni = 0; ni < 4; ni++) {
                    mma16816h(acc[mi][ni], ah[mi], bh[ni][0], bh[ni][1]);
                    mma16816h(acc[mi][ni], ah[mi], bl[ni][0], bl[ni][1]);
                }
        }
    }

    const float alpha = lam[lidx];
    const int r  = lane >> 2;
    const int cc = (lane & 3) * 2;
#pragma unroll
    for (int mi = 0; mi < 4; mi++)
#pragma unroll
        for (int ni = 0; ni < 4; ni++) {
            const int row = m0 + wm0 + mi * 16 + r;
            const int col = n0 + wn0 + ni * 8 + cc;
            float2 w0; w0.x = alpha * acc[mi][ni][0]; w0.y = alpha * acc[mi][ni][1];
            float2 w1; w1.x = alpha * acc[mi][ni][2]; w1.y = alpha * acc[mi][ni][3];
            *(float2*)(C + (size_t)row * N + col) = w0;
            *(float2*)(C + (size_t)(row + 8) * N + col) = w1;
        }
}

// ------------- postprocess: rmsnorm + rotary + gates + ve; fp16 out --------
__global__ __launch_bounds__(256) void postproc_kernel(
    const float* __restrict__ x, const float* __restrict__ ve,
    const float* __restrict__ ve_gate_w, const float* __restrict__ attn_gate_w,
    const float* __restrict__ cosb, const float* __restrict__ sinb)
{
    const int t    = blockIdx.x;
    const int w    = threadIdx.x >> 5;
    const int lane = threadIdx.x & 31;
    const float* base = g_qkv + (size_t)t * (3 * DIM_);
    const size_t ob = (size_t)t * DIM_ + w * D_;

    const float c0 = cosb[t * 64 + lane],      s0 = sinb[t * 64 + lane];
    const float c1 = cosb[t * 64 + lane + 32], s1 = sinb[t * 64 + lane + 32];

    {
        const float* qb = base + w * D_;
        float a0 = qb[lane], a1 = qb[lane + 32], a2 = qb[lane + 64], a3 = qb[lane + 96];
        float ss = a0*a0 + a1*a1 + a2*a2 + a3*a3;
#pragma unroll
        for (int off = 16; off; off >>= 1) ss += __shfl_xor_sync(0xffffffffu, ss, off);
        float r = rsqrtf(ss * (1.0f / 128.0f) + 1e-6f);
        a0 *= r; a1 *= r; a2 *= r; a3 *= r;
        g_q16[ob + lane]      = __float2half_rn( a0 * c0 + a2 * s0);
        g_q16[ob + lane + 32] = __float2half_rn( a1 * c1 + a3 * s1);
        g_q16[ob + lane + 64] = __float2half_rn(-a0 * s0 + a2 * c0);
        g_q16[ob + lane + 96] = __float2half_rn(-a1 * s1 + a3 * c1);
    }
    {
        const float* kb = base + DIM_ + w * D_;
        float a0 = kb[lane], a1 = kb[lane + 32], a2 = kb[lane + 64], a3 = kb[lane + 96];
        float ss = a0*a0 + a1*a1 + a2*a2 + a3*a3;
#pragma unroll
        for (int off = 16; off; off >>= 1) ss += __shfl_xor_sync(0xffffffffu, ss, off);
        float r = rsqrtf(ss * (1.0f / 128.0f) + 1e-6f);
        a0 *= r; a1 *= r; a2 *= r; a3 *= r;
        g_k16[ob + lane]      = __float2half_rn( a0 * c0 + a2 * s0);
        g_k16[ob + lane + 32] = __float2half_rn( a1 * c1 + a3 * s1);
        g_k16[ob + lane + 64] = __float2half_rn(-a0 * s0 + a2 * c0);
        g_k16[ob + lane + 96] = __float2half_rn(-a1 * s1 + a3 * c1);
    }
    float xv = (lane < 16) ? x[(size_t)t * DIM_ + lane] : 0.f;
    float dv = (lane < 16) ? xv * ve_gate_w[w * 16 + lane]   : 0.f;
    float da = (lane < 16) ? xv * attn_gate_w[w * 16 + lane] : 0.f;
#pragma unroll
    for (int off = 16; off; off >>= 1) {
        dv += __shfl_xor_sync(0xffffffffu, dv, off);
        da += __shfl_xor_sync(0xffffffffu, da, off);
    }
    const float veg = 2.0f / (1.0f + __expf(-dv));
    if (lane == 0) g_gate[t * H_ + w] = 1.0f / (1.0f + __expf(-da));
    {
        const float* vb  = base + 2 * DIM_ + w * D_;
        const float* vp2 = ve + ob;
        g_v16[ob + lane]      = __float2half_rn(vb[lane]      + veg * vp2[lane]);
        g_v16[ob + lane + 32] = __float2half_rn(vb[lane + 32] + veg * vp2[lane + 32]);
        g_v16[ob + lane + 64] = __float2half_rn(vb[lane + 64] + veg * vp2[lane + 64]);
        g_v16[ob + lane + 96] = __float2half_rn(vb[lane + 96] + veg * vp2[lane + 96]);
    }
}

// ============================================================================
// flash attention: single-fp16, bounded-logit static softmax (no running max,
// no rescale; P scaled by 2^15 via exp(s - 2.4028)). 3 CTAs/SM, heavy-first.
// ============================================================================
#define KSTR2 136
#define QH_ 0
#define KH_ 8704
#define VH_ 17408
#define KSEG_B 52224
#define ATTN2_SMEM (52224 + 256)

__global__ __launch_bounds__(128, 3) void attn_mma(
    const int* __restrict__ seg, const int* __restrict__ bm_ptr)
{
    extern __shared__ __align__(128) __half sm2[];
    int* kseg = (int*)((char*)sm2 + KSEG_B);
    const unsigned sb = (unsigned)__cvta_generic_to_shared(sm2);
    const int h   = blockIdx.y;
    const int m0  = ((int)gridDim.x - 1 - (int)blockIdx.x) * 64;  // heavy first
    const int tid = threadIdx.x;
    const int wid = tid >> 5, lane = tid & 31;
    const int bm  = bm_ptr[0];
    const int wr  = wid * 16;

    // stage Q tile via cp.async (64 rows x 128 cols = 1024 uint4 slots)
#pragma unroll
    for (int i = 0; i < 8; i++) {
        int f = tid + i * 128;
        int r = f >> 4, u = f & 15;
        size_t ga = (size_t)(m0 + r) * DIM_ + h * D_ + u * 8;
        cpa16(sb + (unsigned)(QH_ + r * KSTR2 + u * 8) * 2, g_q16 + ga);
    }
    CP_COMMIT();

    const int r_ = lane >> 2, c_ = lane & 3;
    const int tq0 = m0 + wr + r_, tq1 = tq0 + 8;
    const int sq0 = seg[tq0], sq1 = seg[tq1];

    float li0 = 0.f, li1 = 0.f;       // scaled by 2^15, same as O
    float o[16][4];
#pragma unroll
    for (int t = 0; t < 16; t++)
#pragma unroll
        for (int e = 0; e < 4; e++) o[t][e] = 0.f;

    const unsigned a_addr = sb + (unsigned)(QH_ + (wr + (lane & 15)) * KSTR2 + (lane >> 4) * 8) * 2;
    const int g  = lane >> 3, gl = lane & 7;
    const unsigned kb_addr = sb + (unsigned)(KH_ + ((g >> 1) * 8 + gl) * KSTR2 + (g & 1) * 8) * 2;
    const unsigned vb_addr = sb + (unsigned)(VH_ + ((g & 1) * 8 + gl) * KSTR2 + (g >> 1) * 8) * 2;

    const int qs0 = seg[m0], qs1 = seg[m0 + 63];
    int kb_lo = m0 - bm; if (kb_lo < 0) kb_lo = 0; kb_lo >>= 6;
    const int kb_hi = m0 >> 6;

    for (int kb = kb_lo; kb <= kb_hi; kb++) {
        const int s0 = kb * 64;
        if (seg[s0 + 63] < qs0 || seg[s0] > qs1) continue;

        __syncthreads();   // prior readers done before restage
#pragma unroll
        for (int i = 0; i < 8; i++) {
            int f = tid + i * 128;
            int r = f >> 4, u = f & 15;
            int t = s0 + r;
            int ts = ((u >> 2) & 1) ? (t > 0 ? t - 1 : 0) : t;
            size_t gk = (size_t)ts * DIM_ + h * D_ + u * 8;
            size_t gv = (size_t)t  * DIM_ + h * D_ + u * 8;
            cpa16(sb + (unsigned)(KH_ + r * KSTR2 + u * 8) * 2, g_k16 + gk);
            cpa16(sb + (unsigned)(VH_ + r * KSTR2 + u * 8) * 2, g_v16 + gv);
        }
        CP_COMMIT();
        if (tid < 64) kseg[tid] = seg[s0 + tid];
        CP_WAIT0();
        __syncthreads();

        // ---- S = Q K^T (single fp16) ----
        float s[8][4];
#pragma unroll
        for (int j = 0; j < 8; j++)
#pragma unroll
            for (int e = 0; e < 4; e++) s[j][e] = 0.f;

#pragma unroll
        for (int kk = 0; kk < 8; kk++) {
            unsigned ah[4];
            ldmx4(ah, a_addr + kk * 32);
#pragma unroll
            for (int jp = 0; jp < 4; jp++) {
                unsigned bh[4];
                ldmx4(bh, kb_addr + (unsigned)(jp * 16 * KSTR2) * 2 + kk * 32);
                mma16816h(s[2*jp],   ah, bh[0], bh[1]);
                mma16816h(s[2*jp+1], ah, bh[2], bh[3]);
            }
        }

        // ---- mask + static softmax: p' = exp(0.1*s - 12.8) * 2^15 ----
        // (logit bound |0.1*s| <= 12.8 after rmsnorm; 12.8 - ln(32768) = 2.4028)
#pragma unroll
        for (int j = 0; j < 8; j++) {
            const int nb = 8 * j + 2 * c_;
            const int tk0 = s0 + nb, tk1 = tk0 + 1;
            const int ka = kseg[nb], kb2 = kseg[nb + 1];
            bool v00 = (tk0 <= tq0) && (tk0 >= tq0 - bm) && (ka  == sq0);
            bool v01 = (tk1 <= tq0) && (tk1 >= tq0 - bm) && (kb2 == sq0);
            bool v10 = (tk0 <= tq1) && (tk0 >= tq1 - bm) && (ka  == sq1);
            bool v11 = (tk1 <= tq1) && (tk1 >= tq1 - bm) && (kb2 == sq1);
            s[j][0] = v00 ? __expf(s[j][0] * 0.1f - 2.4028f) : 0.f;
            s[j][1] = v01 ? __expf(s[j][1] * 0.1f - 2.4028f) : 0.f;
            s[j][2] = v10 ? __expf(s[j][2] * 0.1f - 2.4028f) : 0.f;
            s[j][3] = v11 ? __expf(s[j][3] * 0.1f - 2.4028f) : 0.f;
            li0 += s[j][0] + s[j][1];
            li1 += s[j][2] + s[j][3];
        }

        // ---- O += P V (single fp16) ----
#pragma unroll
        for (int ss = 0; ss < 4; ss++) {
            unsigned pha[4];
            pha[0] = pack2h(s[2*ss][0],   s[2*ss][1]);
            pha[1] = pack2h(s[2*ss][2],   s[2*ss][3]);
            pha[2] = pack2h(s[2*ss+1][0], s[2*ss+1][1]);
            pha[3] = pack2h(s[2*ss+1][2], s[2*ss+1][3]);
#pragma unroll
            for (int dp = 0; dp < 8; dp++) {
                unsigned bh[4];
                ldmx4t(bh, vb_addr + (unsigned)(ss * 16 * KSTR2) * 2 + dp * 32);
                mma16816h(o[2*dp],   pha, bh[0], bh[1]);
                mma16816h(o[2*dp+1], pha, bh[2], bh[3]);
            }
        }
    }

    // ---- epilogue: reduce l over quad, normalize, gate, store fp16 ----
    li0 += __shfl_xor_sync(0xffffffffu, li0, 1);
    li0 += __shfl_xor_sync(0xffffffffu, li0, 2);
    li1 += __shfl_xor_sync(0xffffffffu, li1, 1);
    li1 += __shfl_xor_sync(0xffffffffu, li1, 2);
    const float gg0 = g_gate[tq0 * H_ + h], gg1 = g_gate[tq1 * H_ + h];
    const float i0 = gg0 / li0, i1 = gg1 / li1;
#pragma unroll
    for (int t = 0; t < 16; t++) {
        size_t idx0 = (size_t)tq0 * DIM_ + h * D_ + 8 * t + 2 * c_;
        size_t idx1 = (size_t)tq1 * DIM_ + h * D_ + 8 * t + 2 * c_;
        *(unsigned*)(g_y16 + idx0) = pack2h(o[t][0] * i0, o[t][1] * i0);
        *(unsigned*)(g_y16 + idx1) = pack2h(o[t][2] * i1, o[t][3] * i1);
    }
}

// ---------------------------------------------------------------------------
extern "C" void kernel_launch(void* const* d_in, const int* in_sizes, int n_in,
                              void* d_out, int out_size)
{
    const float* x    = (const float*)d_in[0];
    const float* qkvo = (const float*)d_in[1];
    const float* lam  = (const float*)d_in[2];
    const float* ve   = (const float*)d_in[3];
    const float* agw  = (const float*)d_in[4];
    const float* vgw  = (const float*)d_in[5];
    const float* cosb = (const float*)d_in[6];
    const float* sinb = (const float*)d_in[7];
    const int*   seg  = (const int*)d_in[8];
    const int*   bmp  = (const int*)d_in[9];
    float*       out  = (float*)d_out;

    float *p_qkv;
    __half *p_x16, *p_wh, *p_wl, *p_y16;
    cudaGetSymbolAddress((void**)&p_qkv, g_qkv);
    cudaGetSymbolAddress((void**)&p_x16, g_x16);
    cudaGetSymbolAddress((void**)&p_wh,  g_w16h);
    cudaGetSymbolAddress((void**)&p_wl,  g_w16l);
    cudaGetSymbolAddress((void**)&p_y16, g_y16);

    cudaFuncSetAttribute(gemm_f16s,
                         cudaFuncAttributeMaxDynamicSharedMemorySize, GEMM_SMEM);
    cudaFuncSetAttribute(attn_mma,
                         cudaFuncAttributeMaxDynamicSharedMemorySize, ATTN2_SMEM);

    // 0. one-time conversions
    convert_h<<<T_ * DIM_ / 1024, 256>>>((const float4*)x,
                                         (uint2*)p_x16, T_ * DIM_ / 4);
    convert_split_h<<<4 * DIM_ * DIM_ / 1024, 256>>>(
        (const float4*)qkvo, (uint2*)p_wh, (uint2*)p_wl, 4 * DIM_ * DIM_ / 4);

    // 1. qkv = lam0 * x @ Wqkv^T   [3072 x 3072]
    gemm_f16s<<<dim3(24, 24), 256, GEMM_SMEM>>>(p_x16, p_wh, p_wl,
                                                p_qkv, 3072, lam, 0);

    // 2. rmsnorm + rotary + gates + ve add -> fp16 planes
    postproc_kernel<<<T_, 256>>>(x, ve, vgw, agw, cosb, sinb);

    // 3. attention (static softmax; 3 CTAs/SM; k-shift fused; heavy-first)
    attn_mma<<<dim3(T_ / 64, H_), 128, ATTN2_SMEM>>>(seg, bmp);

    // 4. out = lam1 * y @ Wo^T   [3072 x 1024]
    gemm_f16s<<<dim3(8, 24), 256, GEMM_SMEM>>>(
        p_y16, p_wh + (size_t)3 * DIM_ * DIM_, p_wl + (size_t)3 * DIM_ * DIM_,
        out, 1024, lam, 1);
}